// round 2
// baseline (speedup 1.0000x reference)
#include <cuda_runtime.h>
#include <cuda_bf16.h>
#include <cstdint>

// Problem constants
constexpr int Bc = 8;
constexpr int Tc = 2048;
constexpr int Dc = 1024;
constexpr int Hc = 64;

// Scratch for q, k, v projections (device globals: allocation-free)
__device__ float g_q[Bc * Tc * Hc];
__device__ float g_k[Bc * Tc * Hc];
__device__ float g_v[Bc * Tc * Hc];

// ---------------------------------------------------------------------------
// Projection GEMM: out[M, 64] = x[M, 1024] @ W[1024, 64] + b
// M = B*T = 16384. BM=128, BN=64(=Hc), BK=16, 128 threads, 8x8 microtile.
// blockIdx.y selects {q, k, v}.
// ---------------------------------------------------------------------------
#define PBM 128
#define PBK 16

__global__ __launch_bounds__(128) void proj_kernel(
    const float* __restrict__ x,
    const float* __restrict__ Wq, const float* __restrict__ Wk, const float* __restrict__ Wv,
    const float* __restrict__ bq, const float* __restrict__ bk, const float* __restrict__ bv)
{
    __shared__ float Xs[PBK][PBM];   // x tile, transposed (k-major)
    __shared__ float Ws[PBK][Hc];    // W tile (k-major, natural)

    const float* W;
    const float* bias;
    float* out;
    if (blockIdx.y == 0)      { W = Wq; bias = bq; out = g_q; }
    else if (blockIdx.y == 1) { W = Wk; bias = bk; out = g_k; }
    else                      { W = Wv; bias = bv; out = g_v; }

    const int t  = threadIdx.x;
    const int tr = t >> 3;   // 0..15 -> 8 rows each
    const int tc = t & 7;    // 0..7  -> 8 cols each
    const int m0 = blockIdx.x * PBM;

    float acc[8][8];
#pragma unroll
    for (int r = 0; r < 8; r++)
#pragma unroll
        for (int c = 0; c < 8; c++) acc[r][c] = 0.f;

    for (int k0 = 0; k0 < Dc; k0 += PBK) {
        // X tile: each thread loads one full row of 16 floats, stores transposed
        {
            const float4* xrow = (const float4*)(x + (size_t)(m0 + t) * Dc + k0);
#pragma unroll
            for (int i = 0; i < 4; i++) {
                float4 v = xrow[i];
                Xs[i * 4 + 0][t] = v.x;
                Xs[i * 4 + 1][t] = v.y;
                Xs[i * 4 + 2][t] = v.z;
                Xs[i * 4 + 3][t] = v.w;
            }
        }
        // W tile: 16x64 floats = 256 float4, 2 per thread
        {
#pragma unroll
            for (int i = 0; i < 2; i++) {
                int idx4 = t * 2 + i;
                int kk = idx4 >> 4;
                int c4 = (idx4 & 15) << 2;
                *(float4*)&Ws[kk][c4] = *(const float4*)(W + (size_t)(k0 + kk) * Hc + c4);
            }
        }
        __syncthreads();

#pragma unroll
        for (int kk = 0; kk < PBK; kk++) {
            float a[8], bb[8];
            *(float4*)&a[0]  = *(float4*)&Xs[kk][tr * 8];
            *(float4*)&a[4]  = *(float4*)&Xs[kk][tr * 8 + 4];
            *(float4*)&bb[0] = *(float4*)&Ws[kk][tc * 8];
            *(float4*)&bb[4] = *(float4*)&Ws[kk][tc * 8 + 4];
#pragma unroll
            for (int r = 0; r < 8; r++)
#pragma unroll
                for (int c = 0; c < 8; c++)
                    acc[r][c] += a[r] * bb[c];
        }
        __syncthreads();
    }

    // Epilogue: add bias, write out
    float bb[8];
    *(float4*)&bb[0] = *(const float4*)(bias + tc * 8);
    *(float4*)&bb[4] = *(const float4*)(bias + tc * 8 + 4);
#pragma unroll
    for (int r = 0; r < 8; r++) {
        int m = m0 + tr * 8 + r;
        float4 o0 = make_float4(acc[r][0] + bb[0], acc[r][1] + bb[1],
                                acc[r][2] + bb[2], acc[r][3] + bb[3]);
        float4 o1 = make_float4(acc[r][4] + bb[4], acc[r][5] + bb[5],
                                acc[r][6] + bb[6], acc[r][7] + bb[7]);
        *(float4*)(out + (size_t)m * Hc + tc * 8)     = o0;
        *(float4*)(out + (size_t)m * Hc + tc * 8 + 4) = o1;
    }
}

// ---------------------------------------------------------------------------
// Causal flash attention, fp32.
// Per block: one 64-query tile of one batch. 256 threads (16x16), 4x4 micro.
// Online softmax. Skips fully-masked KV tiles. Heavy tiles scheduled first.
// ---------------------------------------------------------------------------
#define AT  64
#define PAD 68
#define ASMEM (4 * AT * PAD * 4)   // 4 buffers of 64x68 floats = 69632 bytes

__global__ __launch_bounds__(256) void attn_kernel(float* __restrict__ out)
{
    extern __shared__ float sm[];
    float* QsT = sm;                 // [h][q_local], scaled by 1/sqrt(H)
    float* KsT = sm + AT * PAD;      // [h][k_local]
    float* Vs  = sm + 2 * AT * PAD;  // [k_local][h]
    float* Ps  = sm + 3 * AT * PAD;  // [q_local][k_local]

    const int b  = blockIdx.y;
    const int mt = gridDim.x - 1 - blockIdx.x;  // heavy tiles first
    const int q0 = mt * AT;

    const int t  = threadIdx.x;
    const int ty = t >> 4;   // 0..15: query rows 4*ty..+3
    const int tx = t & 15;   // 0..15: key/head cols 4*tx..+3

    const float* qb = g_q + (size_t)b * Tc * Hc;
    const float* kb = g_k + (size_t)b * Tc * Hc;
    const float* vb = g_v + (size_t)b * Tc * Hc;

    // Load Q tile, transposed + pre-scaled
    {
        int row  = t >> 2;   // 0..63
        int part = t & 3;    // 0..3
        const float4* src = (const float4*)(qb + (size_t)(q0 + row) * Hc + part * 16);
#pragma unroll
        for (int i = 0; i < 4; i++) {
            float4 v = src[i];
            int h = part * 16 + i * 4;
            QsT[(h + 0) * PAD + row] = v.x * 0.125f;
            QsT[(h + 1) * PAD + row] = v.y * 0.125f;
            QsT[(h + 2) * PAD + row] = v.z * 0.125f;
            QsT[(h + 3) * PAD + row] = v.w * 0.125f;
        }
    }

    float m[4], l[4], o[4][4];
#pragma unroll
    for (int r = 0; r < 4; r++) {
        m[r] = -1e30f;
        l[r] = 0.f;
#pragma unroll
        for (int c = 0; c < 4; c++) o[r][c] = 0.f;
    }

    for (int kt = 0; kt <= mt; kt++) {
        const int kn0 = kt * AT;
        __syncthreads();  // previous PV done before overwriting K/V/P

        // Load K (transposed) and V (natural) tiles
        {
            int row  = t >> 2;
            int part = t & 3;
            const float4* ks = (const float4*)(kb + (size_t)(kn0 + row) * Hc + part * 16);
            const float4* vs = (const float4*)(vb + (size_t)(kn0 + row) * Hc + part * 16);
#pragma unroll
            for (int i = 0; i < 4; i++) {
                float4 v = ks[i];
                int h = part * 16 + i * 4;
                KsT[(h + 0) * PAD + row] = v.x;
                KsT[(h + 1) * PAD + row] = v.y;
                KsT[(h + 2) * PAD + row] = v.z;
                KsT[(h + 3) * PAD + row] = v.w;
                float4 w = vs[i];
                *(float4*)&Vs[row * PAD + h] = w;
            }
        }
        __syncthreads();

        // S = Q @ K^T (scaled)
        float s[4][4];
#pragma unroll
        for (int r = 0; r < 4; r++)
#pragma unroll
            for (int c = 0; c < 4; c++) s[r][c] = 0.f;

#pragma unroll 16
        for (int k = 0; k < AT; k++) {
            float a[4], bb[4];
            *(float4*)a  = *(float4*)&QsT[k * PAD + 4 * ty];
            *(float4*)bb = *(float4*)&KsT[k * PAD + 4 * tx];
#pragma unroll
            for (int r = 0; r < 4; r++)
#pragma unroll
                for (int c = 0; c < 4; c++)
                    s[r][c] += a[r] * bb[c];
        }

        // Causal mask on the diagonal tile only
        if (kt == mt) {
#pragma unroll
            for (int r = 0; r < 4; r++)
#pragma unroll
                for (int c = 0; c < 4; c++)
                    if (kn0 + 4 * tx + c > q0 + 4 * ty + r) s[r][c] = -1e30f;
        }

        // Online softmax (row reductions across the 16-lane tx group)
#pragma unroll
        for (int r = 0; r < 4; r++) {
            float mx = s[r][0];
#pragma unroll
            for (int c = 1; c < 4; c++) mx = fmaxf(mx, s[r][c]);
#pragma unroll
            for (int off = 1; off < 16; off <<= 1)
                mx = fmaxf(mx, __shfl_xor_sync(0xffffffffu, mx, off));
            float mnew  = fmaxf(m[r], mx);
            float scale = __expf(m[r] - mnew);
            float rs = 0.f;
#pragma unroll
            for (int c = 0; c < 4; c++) {
                float p = __expf(s[r][c] - mnew);
                s[r][c] = p;
                rs += p;
            }
#pragma unroll
            for (int off = 1; off < 16; off <<= 1)
                rs += __shfl_xor_sync(0xffffffffu, rs, off);
            l[r] = l[r] * scale + rs;
            m[r] = mnew;
#pragma unroll
            for (int c = 0; c < 4; c++) o[r][c] *= scale;
        }

        // Write P
#pragma unroll
        for (int r = 0; r < 4; r++)
            *(float4*)&Ps[(4 * ty + r) * PAD + 4 * tx] = *(float4*)&s[r][0];
        __syncthreads();

        // O += P @ V
#pragma unroll 16
        for (int k = 0; k < AT; k++) {
            float vv[4];
            *(float4*)vv = *(float4*)&Vs[k * PAD + 4 * tx];
            float p0 = Ps[(4 * ty + 0) * PAD + k];
            float p1 = Ps[(4 * ty + 1) * PAD + k];
            float p2 = Ps[(4 * ty + 2) * PAD + k];
            float p3 = Ps[(4 * ty + 3) * PAD + k];
#pragma unroll
            for (int c = 0; c < 4; c++) {
                o[0][c] += p0 * vv[c];
                o[1][c] += p1 * vv[c];
                o[2][c] += p2 * vv[c];
                o[3][c] += p3 * vv[c];
            }
        }
    }

    // Epilogue: normalize and store
#pragma unroll
    for (int r = 0; r < 4; r++) {
        float inv = 1.f / l[r];
        int q = q0 + 4 * ty + r;
        float4 ov = make_float4(o[r][0] * inv, o[r][1] * inv,
                                o[r][2] * inv, o[r][3] * inv);
        *(float4*)(out + ((size_t)b * Tc + q) * Hc + 4 * tx) = ov;
    }
}

// ---------------------------------------------------------------------------
// Launch
// ---------------------------------------------------------------------------
extern "C" void kernel_launch(void* const* d_in, const int* in_sizes, int n_in,
                              void* d_out, int out_size)
{
    (void)in_sizes; (void)n_in; (void)out_size;
    const float* x  = (const float*)d_in[0];
    const float* Wk = (const float*)d_in[1];
    const float* bk = (const float*)d_in[2];
    const float* Wq = (const float*)d_in[3];
    const float* bq = (const float*)d_in[4];
    const float* Wv = (const float*)d_in[5];
    const float* bv = (const float*)d_in[6];
    float* out = (float*)d_out;

    cudaFuncSetAttribute(attn_kernel, cudaFuncAttributeMaxDynamicSharedMemorySize, ASMEM);

    dim3 pg((Bc * Tc) / PBM, 3);
    proj_kernel<<<pg, 128>>>(x, Wq, Wk, Wv, bq, bk, bv);

    dim3 ag(Tc / AT, Bc);
    attn_kernel<<<ag, 256, ASMEM>>>(out);
}

// round 3
// speedup vs baseline: 2.2553x; 2.2553x over previous
#include <cuda_runtime.h>
#include <cuda_bf16.h>
#include <cstdint>

constexpr int Bc = 8;
constexpr int Tc = 2048;
constexpr int Dc = 1024;
constexpr int Hc = 64;

__device__ float g_q[Bc * Tc * Hc];
__device__ float g_k[Bc * Tc * Hc];
__device__ float g_v[Bc * Tc * Hc];

__device__ __forceinline__ uint32_t f2tf32(float x) {
    uint32_t u;
    asm("cvt.rna.tf32.f32 %0, %1;" : "=r"(u) : "f"(x));
    return u;
}
__device__ __forceinline__ float ex2f(float x) {
    float y;
    asm("ex2.approx.ftz.f32 %0, %1;" : "=f"(y) : "f"(x));
    return y;
}
__device__ __forceinline__ void mma_tf32(float* c,
    uint32_t a0, uint32_t a1, uint32_t a2, uint32_t a3,
    uint32_t b0, uint32_t b1)
{
    asm volatile(
        "mma.sync.aligned.m16n8k8.row.col.f32.tf32.tf32.f32 "
        "{%0,%1,%2,%3}, {%4,%5,%6,%7}, {%8,%9}, {%0,%1,%2,%3};"
        : "+f"(c[0]), "+f"(c[1]), "+f"(c[2]), "+f"(c[3])
        : "r"(a0), "r"(a1), "r"(a2), "r"(a3), "r"(b0), "r"(b1));
}

// ---------------------------------------------------------------------------
// Projection: out[16384, 64] = x[16384, 1024] @ W[1024, 64] + b   (tf32 mma)
// 128 threads = 4 warps. Warp owns 32 rows (two m16 tiles, shared B frags).
// BK = 32 (4 k8 steps). blockIdx.y selects q/k/v.
// ---------------------------------------------------------------------------
#define PBM 128
#define PBK 32
#define XPAD 36
#define WPAD 68

__global__ __launch_bounds__(128) void proj_kernel(
    const float* __restrict__ x,
    const float* __restrict__ Wq, const float* __restrict__ Wk, const float* __restrict__ Wv,
    const float* __restrict__ bq, const float* __restrict__ bk, const float* __restrict__ bv)
{
    __shared__ float Xs[PBM * XPAD];   // [row][k], pad 36 -> conflict-free frag loads
    __shared__ float Ws[PBK * WPAD];   // [k][n],  pad 68

    const float* W;
    const float* bias;
    float* out;
    if (blockIdx.y == 0)      { W = Wq; bias = bq; out = g_q; }
    else if (blockIdx.y == 1) { W = Wk; bias = bk; out = g_k; }
    else                      { W = Wv; bias = bv; out = g_v; }

    const int t    = threadIdx.x;
    const int w    = t >> 5;
    const int lane = t & 31;
    const int g    = lane >> 2;
    const int q4   = lane & 3;
    const int m0   = blockIdx.x * PBM;

    float acc[2][8][4];
#pragma unroll
    for (int i = 0; i < 2; i++)
#pragma unroll
        for (int nf = 0; nf < 8; nf++)
#pragma unroll
            for (int j = 0; j < 4; j++) acc[i][nf][j] = 0.f;

    for (int k0 = 0; k0 < Dc; k0 += PBK) {
        // stage x tile [128][32] (tf32-rounded)
#pragma unroll
        for (int i = 0; i < 8; i++) {
            int idx = t + i * 128;            // 1024 float4-units / 128 threads... (128*32/4=1024)
            int row = idx >> 3;
            int c4  = (idx & 7) << 2;
            float4 v = *(const float4*)(x + (size_t)(m0 + row) * Dc + k0 + c4);
            float* d = &Xs[row * XPAD + c4];
            d[0] = __uint_as_float(f2tf32(v.x));
            d[1] = __uint_as_float(f2tf32(v.y));
            d[2] = __uint_as_float(f2tf32(v.z));
            d[3] = __uint_as_float(f2tf32(v.w));
        }
        // stage W tile [32][64]
#pragma unroll
        for (int i = 0; i < 4; i++) {
            int idx = t + i * 128;            // 512 float4-units
            int row = idx >> 4;
            int c4  = (idx & 15) << 2;
            float4 v = *(const float4*)(W + (size_t)(k0 + row) * Hc + c4);
            float* d = &Ws[row * WPAD + c4];
            d[0] = __uint_as_float(f2tf32(v.x));
            d[1] = __uint_as_float(f2tf32(v.y));
            d[2] = __uint_as_float(f2tf32(v.z));
            d[3] = __uint_as_float(f2tf32(v.w));
        }
        __syncthreads();

#pragma unroll
        for (int ks = 0; ks < 4; ks++) {
            const int kc = ks * 8 + q4;
            uint32_t a[2][4];
#pragma unroll
            for (int i = 0; i < 2; i++) {
                int r = w * 32 + i * 16 + g;
                a[i][0] = __float_as_uint(Xs[(r    ) * XPAD + kc]);
                a[i][1] = __float_as_uint(Xs[(r + 8) * XPAD + kc]);
                a[i][2] = __float_as_uint(Xs[(r    ) * XPAD + kc + 4]);
                a[i][3] = __float_as_uint(Xs[(r + 8) * XPAD + kc + 4]);
            }
#pragma unroll
            for (int nf = 0; nf < 8; nf++) {
                uint32_t b0 = __float_as_uint(Ws[(ks * 8 + q4    ) * WPAD + nf * 8 + g]);
                uint32_t b1 = __float_as_uint(Ws[(ks * 8 + q4 + 4) * WPAD + nf * 8 + g]);
                mma_tf32(acc[0][nf], a[0][0], a[0][1], a[0][2], a[0][3], b0, b1);
                mma_tf32(acc[1][nf], a[1][0], a[1][1], a[1][2], a[1][3], b0, b1);
            }
        }
        __syncthreads();
    }

    // epilogue: bias + store (f32)
#pragma unroll
    for (int i = 0; i < 2; i++) {
        int r0 = m0 + w * 32 + i * 16 + g;
#pragma unroll
        for (int nf = 0; nf < 8; nf++) {
            int col = nf * 8 + 2 * q4;
            float b0 = bias[col], b1 = bias[col + 1];
            float2 v0 = make_float2(acc[i][nf][0] + b0, acc[i][nf][1] + b1);
            float2 v1 = make_float2(acc[i][nf][2] + b0, acc[i][nf][3] + b1);
            *(float2*)(out + (size_t)r0 * Hc + col)       = v0;
            *(float2*)(out + (size_t)(r0 + 8) * Hc + col) = v1;
        }
    }
}

// ---------------------------------------------------------------------------
// Causal flash attention, tf32 mma. Block = 64 queries, 4 warps (128 thr).
// Q held in registers as A-fragments. K smem [kv][68]; V smem transposed
// [h][68] (conflict-free B loads). P warp-private smem. exp2-space softmax.
// ---------------------------------------------------------------------------
#define KVPAD 68
#define ASMEM ((2 * 64 * KVPAD + 4 * 16 * KVPAD) * 4)   // 52224 bytes

__global__ __launch_bounds__(128) void attn_kernel(float* __restrict__ out)
{
    extern __shared__ float sm[];
    float* Ks  = sm;                    // [kv][KVPAD]
    float* VsT = sm + 64 * KVPAD;       // [h][KVPAD]
    float* Psw = sm + 2 * 64 * KVPAD;   // per-warp [16][KVPAD]

    const int b  = blockIdx.y;
    const int mt = gridDim.x - 1 - blockIdx.x;   // heavy tiles first
    const int q0 = mt * 64;

    const int t    = threadIdx.x;
    const int w    = t >> 5;
    const int lane = t & 31;
    const int g    = lane >> 2;
    const int q4   = lane & 3;
    float* Pw = Psw + w * 16 * KVPAD;

    const float* qb = g_q + (size_t)b * Tc * Hc;
    const float* kb = g_k + (size_t)b * Tc * Hc;
    const float* vb = g_v + (size_t)b * Tc * Hc;

    // Q A-fragments in registers, pre-scaled by (1/sqrt(H)) * log2(e)
    const float SC = 0.125f * 1.44269504f;
    uint32_t qa[8][4];
    {
        const float* r0 = qb + (size_t)(q0 + w * 16 + g) * Hc;
        const float* r1 = r0 + 8 * Hc;
#pragma unroll
        for (int ks = 0; ks < 8; ks++) {
            qa[ks][0] = f2tf32(r0[ks * 8 + q4] * SC);
            qa[ks][1] = f2tf32(r1[ks * 8 + q4] * SC);
            qa[ks][2] = f2tf32(r0[ks * 8 + q4 + 4] * SC);
            qa[ks][3] = f2tf32(r1[ks * 8 + q4 + 4] * SC);
        }
    }

    float o[8][4];
#pragma unroll
    for (int nf = 0; nf < 8; nf++)
#pragma unroll
        for (int j = 0; j < 4; j++) o[nf][j] = 0.f;
    float m0 = -1e30f, m1 = -1e30f, l0 = 0.f, l1 = 0.f;

    for (int kt = 0; kt <= mt; kt++) {
        const int kn0 = kt * 64;
        __syncthreads();

        // stage K [kv][h] (tf32)
        {
            int row = t >> 1;
            int cb  = (t & 1) * 32;
            const float4* src = (const float4*)(kb + (size_t)(kn0 + row) * Hc + cb);
#pragma unroll
            for (int i = 0; i < 8; i++) {
                float4 v = src[i];
                float* d = &Ks[row * KVPAD + cb + i * 4];
                d[0] = __uint_as_float(f2tf32(v.x));
                d[1] = __uint_as_float(f2tf32(v.y));
                d[2] = __uint_as_float(f2tf32(v.z));
                d[3] = __uint_as_float(f2tf32(v.w));
            }
        }
        // stage V transposed -> VsT[h][kv] (tf32)
        {
            int row = t & 63;
            int cb  = (t >> 6) * 32;
            const float4* src = (const float4*)(vb + (size_t)(kn0 + row) * Hc + cb);
#pragma unroll
            for (int i = 0; i < 8; i++) {
                float4 v = src[i];
                int h = cb + i * 4;
                VsT[(h + 0) * KVPAD + row] = __uint_as_float(f2tf32(v.x));
                VsT[(h + 1) * KVPAD + row] = __uint_as_float(f2tf32(v.y));
                VsT[(h + 2) * KVPAD + row] = __uint_as_float(f2tf32(v.z));
                VsT[(h + 3) * KVPAD + row] = __uint_as_float(f2tf32(v.w));
            }
        }
        __syncthreads();

        // S = Q @ K^T  (in exp2-scaled space)
        float sf[8][4];
#pragma unroll
        for (int nf = 0; nf < 8; nf++) {
            sf[nf][0] = sf[nf][1] = sf[nf][2] = sf[nf][3] = 0.f;
#pragma unroll
            for (int ks = 0; ks < 8; ks++) {
                uint32_t b0 = __float_as_uint(Ks[(nf * 8 + g) * KVPAD + ks * 8 + q4]);
                uint32_t b1 = __float_as_uint(Ks[(nf * 8 + g) * KVPAD + ks * 8 + q4 + 4]);
                mma_tf32(sf[nf], qa[ks][0], qa[ks][1], qa[ks][2], qa[ks][3], b0, b1);
            }
        }

        // causal mask on diagonal tile
        if (kt == mt) {
            const int r0 = q0 + w * 16 + g;
            const int r1 = r0 + 8;
#pragma unroll
            for (int nf = 0; nf < 8; nf++) {
                int c0 = kn0 + nf * 8 + 2 * q4;
                if (c0     > r0) sf[nf][0] = -1e30f;
                if (c0 + 1 > r0) sf[nf][1] = -1e30f;
                if (c0     > r1) sf[nf][2] = -1e30f;
                if (c0 + 1 > r1) sf[nf][3] = -1e30f;
            }
        }

        // online softmax (rows g and g+8 of this warp tile)
        float mx0 = -1e30f, mx1 = -1e30f;
#pragma unroll
        for (int nf = 0; nf < 8; nf++) {
            mx0 = fmaxf(mx0, fmaxf(sf[nf][0], sf[nf][1]));
            mx1 = fmaxf(mx1, fmaxf(sf[nf][2], sf[nf][3]));
        }
        mx0 = fmaxf(mx0, __shfl_xor_sync(0xffffffffu, mx0, 1));
        mx0 = fmaxf(mx0, __shfl_xor_sync(0xffffffffu, mx0, 2));
        mx1 = fmaxf(mx1, __shfl_xor_sync(0xffffffffu, mx1, 1));
        mx1 = fmaxf(mx1, __shfl_xor_sync(0xffffffffu, mx1, 2));

        float mn0 = fmaxf(m0, mx0), mn1 = fmaxf(m1, mx1);
        float sc0 = ex2f(m0 - mn0), sc1 = ex2f(m1 - mn1);

        float rs0 = 0.f, rs1 = 0.f;
#pragma unroll
        for (int nf = 0; nf < 8; nf++) {
            sf[nf][0] = ex2f(sf[nf][0] - mn0);
            sf[nf][1] = ex2f(sf[nf][1] - mn0);
            sf[nf][2] = ex2f(sf[nf][2] - mn1);
            sf[nf][3] = ex2f(sf[nf][3] - mn1);
            rs0 += sf[nf][0] + sf[nf][1];
            rs1 += sf[nf][2] + sf[nf][3];
        }
        rs0 += __shfl_xor_sync(0xffffffffu, rs0, 1);
        rs0 += __shfl_xor_sync(0xffffffffu, rs0, 2);
        rs1 += __shfl_xor_sync(0xffffffffu, rs1, 1);
        rs1 += __shfl_xor_sync(0xffffffffu, rs1, 2);

        l0 = l0 * sc0 + rs0;  m0 = mn0;
        l1 = l1 * sc1 + rs1;  m1 = mn1;
#pragma unroll
        for (int nf = 0; nf < 8; nf++) {
            o[nf][0] *= sc0;  o[nf][1] *= sc0;
            o[nf][2] *= sc1;  o[nf][3] *= sc1;
        }

        // write P (tf32) to warp-private smem
#pragma unroll
        for (int nf = 0; nf < 8; nf++) {
            int c = nf * 8 + 2 * q4;
            float2 p01 = make_float2(__uint_as_float(f2tf32(sf[nf][0])),
                                     __uint_as_float(f2tf32(sf[nf][1])));
            float2 p23 = make_float2(__uint_as_float(f2tf32(sf[nf][2])),
                                     __uint_as_float(f2tf32(sf[nf][3])));
            *(float2*)&Pw[(g    ) * KVPAD + c] = p01;
            *(float2*)&Pw[(g + 8) * KVPAD + c] = p23;
        }
        __syncwarp();

        // O += P @ V
#pragma unroll
        for (int ks = 0; ks < 8; ks++) {
            uint32_t a0 = __float_as_uint(Pw[(g    ) * KVPAD + ks * 8 + q4]);
            uint32_t a1 = __float_as_uint(Pw[(g + 8) * KVPAD + ks * 8 + q4]);
            uint32_t a2 = __float_as_uint(Pw[(g    ) * KVPAD + ks * 8 + q4 + 4]);
            uint32_t a3 = __float_as_uint(Pw[(g + 8) * KVPAD + ks * 8 + q4 + 4]);
#pragma unroll
            for (int nf = 0; nf < 8; nf++) {
                uint32_t b0 = __float_as_uint(VsT[(nf * 8 + g) * KVPAD + ks * 8 + q4]);
                uint32_t b1 = __float_as_uint(VsT[(nf * 8 + g) * KVPAD + ks * 8 + q4 + 4]);
                mma_tf32(o[nf], a0, a1, a2, a3, b0, b1);
            }
        }
    }

    // epilogue
    float inv0 = 1.f / l0, inv1 = 1.f / l1;
    const int r0 = q0 + w * 16 + g;
#pragma unroll
    for (int nf = 0; nf < 8; nf++) {
        int col = nf * 8 + 2 * q4;
        float2 v0 = make_float2(o[nf][0] * inv0, o[nf][1] * inv0);
        float2 v1 = make_float2(o[nf][2] * inv1, o[nf][3] * inv1);
        *(float2*)(out + ((size_t)b * Tc + r0)     * Hc + col) = v0;
        *(float2*)(out + ((size_t)b * Tc + r0 + 8) * Hc + col) = v1;
    }
}

// ---------------------------------------------------------------------------
extern "C" void kernel_launch(void* const* d_in, const int* in_sizes, int n_in,
                              void* d_out, int out_size)
{
    (void)in_sizes; (void)n_in; (void)out_size;
    const float* x  = (const float*)d_in[0];
    const float* Wk = (const float*)d_in[1];
    const float* bk = (const float*)d_in[2];
    const float* Wq = (const float*)d_in[3];
    const float* bq = (const float*)d_in[4];
    const float* Wv = (const float*)d_in[5];
    const float* bv = (const float*)d_in[6];
    float* out = (float*)d_out;

    cudaFuncSetAttribute(attn_kernel, cudaFuncAttributeMaxDynamicSharedMemorySize, ASMEM);

    dim3 pg((Bc * Tc) / PBM, 3);
    proj_kernel<<<pg, 128>>>(x, Wq, Wk, Wv, bq, bk, bv);

    dim3 ag(Tc / 64, Bc);
    attn_kernel<<<ag, 128, ASMEM>>>(out);
}

// round 4
// speedup vs baseline: 2.3791x; 1.0549x over previous
#include <cuda_runtime.h>
#include <cuda_bf16.h>
#include <cstdint>

constexpr int Bc = 8;
constexpr int Tc = 2048;
constexpr int Dc = 1024;
constexpr int Hc = 64;

__device__ float g_q[Bc * Tc * Hc];
__device__ float g_k[Bc * Tc * Hc];
__device__ float g_v[Bc * Tc * Hc];

__device__ __forceinline__ uint32_t f2tf32(float x) {
    uint32_t u;
    asm("cvt.rna.tf32.f32 %0, %1;" : "=r"(u) : "f"(x));
    return u;
}
__device__ __forceinline__ float ex2f(float x) {
    float y;
    asm("ex2.approx.ftz.f32 %0, %1;" : "=f"(y) : "f"(x));
    return y;
}
__device__ __forceinline__ void mma_tf32(float* c,
    uint32_t a0, uint32_t a1, uint32_t a2, uint32_t a3,
    uint32_t b0, uint32_t b1)
{
    asm volatile(
        "mma.sync.aligned.m16n8k8.row.col.f32.tf32.tf32.f32 "
        "{%0,%1,%2,%3}, {%4,%5,%6,%7}, {%8,%9}, {%0,%1,%2,%3};"
        : "+f"(c[0]), "+f"(c[1]), "+f"(c[2]), "+f"(c[3])
        : "r"(a0), "r"(a1), "r"(a2), "r"(a3), "r"(b0), "r"(b1));
}

// ---------------------------------------------------------------------------
// Fused projection: q,k,v[16384,64] = x[16384,1024] @ {Wq,Wk,Wv} + bias.
// BM=64, 4 warps; each warp one m16 row tile, all 3 projections. BK=32.
// x is loaded ONCE (vs 3x before); W tiles come from L2.
// ---------------------------------------------------------------------------
#define FBM 64
#define XPAD 36
#define WPAD 68

__global__ __launch_bounds__(128) void proj_kernel(
    const float* __restrict__ x,
    const float* __restrict__ Wq, const float* __restrict__ Wk, const float* __restrict__ Wv,
    const float* __restrict__ bq, const float* __restrict__ bk, const float* __restrict__ bv)
{
    __shared__ float Xs[FBM * XPAD];        // [row][k]
    __shared__ float Ws[3 * 32 * WPAD];     // [proj][k][n]

    const float* Wp[3] = { Wq, Wk, Wv };

    const int t    = threadIdx.x;
    const int w    = t >> 5;
    const int lane = t & 31;
    const int g    = lane >> 2;
    const int q4   = lane & 3;
    const int m0   = blockIdx.x * FBM;

    float acc[3][8][4];
#pragma unroll
    for (int p = 0; p < 3; p++)
#pragma unroll
        for (int nf = 0; nf < 8; nf++)
#pragma unroll
            for (int j = 0; j < 4; j++) acc[p][nf][j] = 0.f;

    for (int k0 = 0; k0 < Dc; k0 += 32) {
        // stage x tile [64][32] (tf32)
#pragma unroll
        for (int i = 0; i < 4; i++) {
            int idx = t + i * 128;
            int row = idx >> 3;
            int c4  = (idx & 7) << 2;
            float4 v = *(const float4*)(x + (size_t)(m0 + row) * Dc + k0 + c4);
            float* d = &Xs[row * XPAD + c4];
            d[0] = __uint_as_float(f2tf32(v.x));
            d[1] = __uint_as_float(f2tf32(v.y));
            d[2] = __uint_as_float(f2tf32(v.z));
            d[3] = __uint_as_float(f2tf32(v.w));
        }
        // stage 3 W tiles [32][64] each (tf32)
#pragma unroll
        for (int i = 0; i < 12; i++) {
            int idx = t + i * 128;
            int p   = idx >> 9;
            int rem = idx & 511;
            int row = rem >> 4;
            int c4  = (rem & 15) << 2;
            float4 v = *(const float4*)(Wp[p] + (size_t)(k0 + row) * Hc + c4);
            float* d = &Ws[p * 32 * WPAD + row * WPAD + c4];
            d[0] = __uint_as_float(f2tf32(v.x));
            d[1] = __uint_as_float(f2tf32(v.y));
            d[2] = __uint_as_float(f2tf32(v.z));
            d[3] = __uint_as_float(f2tf32(v.w));
        }
        __syncthreads();

#pragma unroll
        for (int ks = 0; ks < 4; ks++) {
            const int kc = ks * 8 + q4;
            const int r  = w * 16 + g;
            uint32_t a0 = __float_as_uint(Xs[(r    ) * XPAD + kc]);
            uint32_t a1 = __float_as_uint(Xs[(r + 8) * XPAD + kc]);
            uint32_t a2 = __float_as_uint(Xs[(r    ) * XPAD + kc + 4]);
            uint32_t a3 = __float_as_uint(Xs[(r + 8) * XPAD + kc + 4]);
#pragma unroll
            for (int p = 0; p < 3; p++)
#pragma unroll
                for (int nf = 0; nf < 8; nf++) {
                    uint32_t b0 = __float_as_uint(Ws[p * 32 * WPAD + (ks * 8 + q4    ) * WPAD + nf * 8 + g]);
                    uint32_t b1 = __float_as_uint(Ws[p * 32 * WPAD + (ks * 8 + q4 + 4) * WPAD + nf * 8 + g]);
                    mma_tf32(acc[p][nf], a0, a1, a2, a3, b0, b1);
                }
        }
        __syncthreads();
    }

    // epilogue
    const float* biases[3] = { bq, bk, bv };
    float* outs[3] = { g_q, g_k, g_v };
    const int r0 = m0 + w * 16 + g;
#pragma unroll
    for (int p = 0; p < 3; p++) {
        float* out = outs[p];
#pragma unroll
        for (int nf = 0; nf < 8; nf++) {
            int col = nf * 8 + 2 * q4;
            float b0 = biases[p][col], b1 = biases[p][col + 1];
            float2 v0 = make_float2(acc[p][nf][0] + b0, acc[p][nf][1] + b1);
            float2 v1 = make_float2(acc[p][nf][2] + b0, acc[p][nf][3] + b1);
            *(float2*)(out + (size_t)r0 * Hc + col)       = v0;
            *(float2*)(out + (size_t)(r0 + 8) * Hc + col) = v1;
        }
    }
}

// ---------------------------------------------------------------------------
// Causal flash attention, tf32 mma, 2-way KV split.
// Block = 64 queries, 8 warps. Warps 0-3 (parity 0) handle even KV tiles,
// warps 4-7 (parity 1) odd KV tiles; each keeps private (m,l,O); merged at
// the end flash-style. Double-buffered K/V staging.
// ---------------------------------------------------------------------------
#define KVPAD 68
#define TILEF (64 * KVPAD)
#define ASMEM ((4 * TILEF + 8 * 16 * KVPAD) * 4)   // 104448 bytes

__global__ __launch_bounds__(256) void attn_kernel(float* __restrict__ out)
{
    extern __shared__ float sm[];
    float* Psw = sm + 4 * TILEF;   // per-warp [16][KVPAD]

    const int b  = blockIdx.y;
    const int mt = gridDim.x - 1 - blockIdx.x;   // heavy tiles first
    const int q0 = mt * 64;

    const int t    = threadIdx.x;
    const int w    = t >> 5;
    const int wq   = w & 3;        // query sub-tile
    const int p    = w >> 2;       // KV parity
    const int lane = t & 31;
    const int g    = lane >> 2;
    const int q4   = lane & 3;

    float* Ks = sm + p * TILEF;            // parity's K buffer
    float* Vs = sm + (2 + p) * TILEF;      // parity's V buffer (transposed)
    float* Pw = Psw + w * 16 * KVPAD;

    const float* qb = g_q + (size_t)b * Tc * Hc;
    const float* kb = g_k + (size_t)b * Tc * Hc;
    const float* vb = g_v + (size_t)b * Tc * Hc;

    // Q A-fragments, pre-scaled by (1/sqrt(H)) * log2(e)
    const float SC = 0.125f * 1.44269504f;
    uint32_t qa[8][4];
    {
        const float* r0 = qb + (size_t)(q0 + wq * 16 + g) * Hc;
        const float* r1 = r0 + 8 * Hc;
#pragma unroll
        for (int ks = 0; ks < 8; ks++) {
            qa[ks][0] = f2tf32(r0[ks * 8 + q4] * SC);
            qa[ks][1] = f2tf32(r1[ks * 8 + q4] * SC);
            qa[ks][2] = f2tf32(r0[ks * 8 + q4 + 4] * SC);
            qa[ks][3] = f2tf32(r1[ks * 8 + q4 + 4] * SC);
        }
    }

    float o[8][4];
#pragma unroll
    for (int nf = 0; nf < 8; nf++)
#pragma unroll
        for (int j = 0; j < 4; j++) o[nf][j] = 0.f;
    float m0 = -1e30f, m1 = -1e30f, l0 = 0.f, l1 = 0.f;

    for (int kt2 = 0; kt2 <= mt; kt2 += 2) {
        __syncthreads();

        // Staging: 4 thread groups of 64, one per buffer.
        {
            const int role = t >> 6;
            const int row  = t & 63;
            if (role == 0 || role == 1) {
                const int kt = kt2 + role;
                if (kt <= mt) {
                    float* dst = sm + role * TILEF + row * KVPAD;
                    const float4* src = (const float4*)(kb + (size_t)(kt * 64 + row) * Hc);
#pragma unroll
                    for (int i = 0; i < 16; i++) {
                        float4 v = src[i];
                        dst[i * 4 + 0] = __uint_as_float(f2tf32(v.x));
                        dst[i * 4 + 1] = __uint_as_float(f2tf32(v.y));
                        dst[i * 4 + 2] = __uint_as_float(f2tf32(v.z));
                        dst[i * 4 + 3] = __uint_as_float(f2tf32(v.w));
                    }
                }
            } else {
                const int kt = kt2 + (role - 2);
                if (kt <= mt) {
                    float* dst = sm + (role) * TILEF;   // roles 2,3 -> V buffers
                    const float4* src = (const float4*)(vb + (size_t)(kt * 64 + row) * Hc);
#pragma unroll
                    for (int i = 0; i < 16; i++) {
                        float4 v = src[i];
                        int h = i * 4;
                        dst[(h + 0) * KVPAD + row] = __uint_as_float(f2tf32(v.x));
                        dst[(h + 1) * KVPAD + row] = __uint_as_float(f2tf32(v.y));
                        dst[(h + 2) * KVPAD + row] = __uint_as_float(f2tf32(v.z));
                        dst[(h + 3) * KVPAD + row] = __uint_as_float(f2tf32(v.w));
                    }
                }
            }
        }
        __syncthreads();

        const int kt = kt2 + p;
        if (kt > mt) continue;
        const int kn0 = kt * 64;

        // S = Q @ K^T (exp2-scaled space)
        float sf[8][4];
#pragma unroll
        for (int nf = 0; nf < 8; nf++) {
            sf[nf][0] = sf[nf][1] = sf[nf][2] = sf[nf][3] = 0.f;
#pragma unroll
            for (int ks = 0; ks < 8; ks++) {
                uint32_t b0 = __float_as_uint(Ks[(nf * 8 + g) * KVPAD + ks * 8 + q4]);
                uint32_t b1 = __float_as_uint(Ks[(nf * 8 + g) * KVPAD + ks * 8 + q4 + 4]);
                mma_tf32(sf[nf], qa[ks][0], qa[ks][1], qa[ks][2], qa[ks][3], b0, b1);
            }
        }

        // causal mask on diagonal tile
        if (kt == mt) {
            const int r0 = q0 + wq * 16 + g;
            const int r1 = r0 + 8;
#pragma unroll
            for (int nf = 0; nf < 8; nf++) {
                int c0 = kn0 + nf * 8 + 2 * q4;
                if (c0     > r0) sf[nf][0] = -1e30f;
                if (c0 + 1 > r0) sf[nf][1] = -1e30f;
                if (c0     > r1) sf[nf][2] = -1e30f;
                if (c0 + 1 > r1) sf[nf][3] = -1e30f;
            }
        }

        // online softmax
        float mx0 = -1e30f, mx1 = -1e30f;
#pragma unroll
        for (int nf = 0; nf < 8; nf++) {
            mx0 = fmaxf(mx0, fmaxf(sf[nf][0], sf[nf][1]));
            mx1 = fmaxf(mx1, fmaxf(sf[nf][2], sf[nf][3]));
        }
        mx0 = fmaxf(mx0, __shfl_xor_sync(0xffffffffu, mx0, 1));
        mx0 = fmaxf(mx0, __shfl_xor_sync(0xffffffffu, mx0, 2));
        mx1 = fmaxf(mx1, __shfl_xor_sync(0xffffffffu, mx1, 1));
        mx1 = fmaxf(mx1, __shfl_xor_sync(0xffffffffu, mx1, 2));

        float mn0 = fmaxf(m0, mx0), mn1 = fmaxf(m1, mx1);
        float sc0 = ex2f(m0 - mn0), sc1 = ex2f(m1 - mn1);

        float rs0 = 0.f, rs1 = 0.f;
#pragma unroll
        for (int nf = 0; nf < 8; nf++) {
            sf[nf][0] = ex2f(sf[nf][0] - mn0);
            sf[nf][1] = ex2f(sf[nf][1] - mn0);
            sf[nf][2] = ex2f(sf[nf][2] - mn1);
            sf[nf][3] = ex2f(sf[nf][3] - mn1);
            rs0 += sf[nf][0] + sf[nf][1];
            rs1 += sf[nf][2] + sf[nf][3];
        }
        rs0 += __shfl_xor_sync(0xffffffffu, rs0, 1);
        rs0 += __shfl_xor_sync(0xffffffffu, rs0, 2);
        rs1 += __shfl_xor_sync(0xffffffffu, rs1, 1);
        rs1 += __shfl_xor_sync(0xffffffffu, rs1, 2);

        l0 = l0 * sc0 + rs0;  m0 = mn0;
        l1 = l1 * sc1 + rs1;  m1 = mn1;
#pragma unroll
        for (int nf = 0; nf < 8; nf++) {
            o[nf][0] *= sc0;  o[nf][1] *= sc0;
            o[nf][2] *= sc1;  o[nf][3] *= sc1;
        }

        // P -> warp-private smem (tf32)
#pragma unroll
        for (int nf = 0; nf < 8; nf++) {
            int c = nf * 8 + 2 * q4;
            float2 p01 = make_float2(__uint_as_float(f2tf32(sf[nf][0])),
                                     __uint_as_float(f2tf32(sf[nf][1])));
            float2 p23 = make_float2(__uint_as_float(f2tf32(sf[nf][2])),
                                     __uint_as_float(f2tf32(sf[nf][3])));
            *(float2*)&Pw[(g    ) * KVPAD + c] = p01;
            *(float2*)&Pw[(g + 8) * KVPAD + c] = p23;
        }
        __syncwarp();

        // O += P @ V
#pragma unroll
        for (int ks = 0; ks < 8; ks++) {
            uint32_t a0 = __float_as_uint(Pw[(g    ) * KVPAD + ks * 8 + q4]);
            uint32_t a1 = __float_as_uint(Pw[(g + 8) * KVPAD + ks * 8 + q4]);
            uint32_t a2 = __float_as_uint(Pw[(g    ) * KVPAD + ks * 8 + q4 + 4]);
            uint32_t a3 = __float_as_uint(Pw[(g + 8) * KVPAD + ks * 8 + q4 + 4]);
#pragma unroll
            for (int nf = 0; nf < 8; nf++) {
                uint32_t b0 = __float_as_uint(Vs[(nf * 8 + g) * KVPAD + ks * 8 + q4]);
                uint32_t b1 = __float_as_uint(Vs[(nf * 8 + g) * KVPAD + ks * 8 + q4 + 4]);
                mma_tf32(o[nf], a0, a1, a2, a3, b0, b1);
            }
        }
    }

    // ---- merge the two KV parities (flash combine) ----
    __syncthreads();
    // lane-scatter area reusing the K/V buffers; stride 37 -> conflict-free
    float* mg = sm;
    if (p == 1) {
        float* dst = mg + (wq * 32 + lane) * 37;
#pragma unroll
        for (int nf = 0; nf < 8; nf++) {
            dst[nf * 4 + 0] = o[nf][0];
            dst[nf * 4 + 1] = o[nf][1];
            dst[nf * 4 + 2] = o[nf][2];
            dst[nf * 4 + 3] = o[nf][3];
        }
        dst[32] = m0; dst[33] = m1; dst[34] = l0; dst[35] = l1;
    }
    __syncthreads();
    if (p == 0) {
        const float* src = mg + (wq * 32 + lane) * 37;
        float mb0 = src[32], mb1 = src[33], lb0 = src[34], lb1 = src[35];
        float mm0 = fmaxf(m0, mb0), mm1 = fmaxf(m1, mb1);
        float sa0 = ex2f(m0 - mm0), sb0 = ex2f(mb0 - mm0);
        float sa1 = ex2f(m1 - mm1), sb1 = ex2f(mb1 - mm1);
        float L0 = l0 * sa0 + lb0 * sb0;
        float L1 = l1 * sa1 + lb1 * sb1;
        float inv0 = 1.f / L0, inv1 = 1.f / L1;

        const int r0 = q0 + wq * 16 + g;
#pragma unroll
        for (int nf = 0; nf < 8; nf++) {
            int col = nf * 8 + 2 * q4;
            float2 v0 = make_float2((o[nf][0] * sa0 + src[nf * 4 + 0] * sb0) * inv0,
                                    (o[nf][1] * sa0 + src[nf * 4 + 1] * sb0) * inv0);
            float2 v1 = make_float2((o[nf][2] * sa1 + src[nf * 4 + 2] * sb1) * inv1,
                                    (o[nf][3] * sa1 + src[nf * 4 + 3] * sb1) * inv1);
            *(float2*)(out + ((size_t)b * Tc + r0)     * Hc + col) = v0;
            *(float2*)(out + ((size_t)b * Tc + r0 + 8) * Hc + col) = v1;
        }
    }
}

// ---------------------------------------------------------------------------
extern "C" void kernel_launch(void* const* d_in, const int* in_sizes, int n_in,
                              void* d_out, int out_size)
{
    (void)in_sizes; (void)n_in; (void)out_size;
    const float* x  = (const float*)d_in[0];
    const float* Wk = (const float*)d_in[1];
    const float* bk = (const float*)d_in[2];
    const float* Wq = (const float*)d_in[3];
    const float* bq = (const float*)d_in[4];
    const float* Wv = (const float*)d_in[5];
    const float* bv = (const float*)d_in[6];
    float* out = (float*)d_out;

    cudaFuncSetAttribute(attn_kernel, cudaFuncAttributeMaxDynamicSharedMemorySize, ASMEM);

    proj_kernel<<<(Bc * Tc) / FBM, 128>>>(x, Wq, Wk, Wv, bq, bk, bv);

    dim3 ag(Tc / 64, Bc);
    attn_kernel<<<ag, 256, ASMEM>>>(out);
}

// round 5
// speedup vs baseline: 2.3938x; 1.0062x over previous
#include <cuda_runtime.h>
#include <cuda_bf16.h>
#include <cstdint>

constexpr int Bc = 8;
constexpr int Tc = 2048;
constexpr int Dc = 1024;
constexpr int Hc = 64;

// q/k/v projections
__device__ float g_q[Bc * Tc * Hc];
__device__ float g_k[Bc * Tc * Hc];
__device__ float g_v[Bc * Tc * Hc];

// split-KV partials: 80 chunk-slots per batch (qtile i has ceil((i+1)/8) chunks)
constexpr int SLOTS = 80;
__device__ float g_po[Bc * SLOTS * 64 * 64];   // unnormalized O
__device__ float g_pm[Bc * SLOTS * 64];        // row max (exp2 space)
__device__ float g_pl[Bc * SLOTS * 64];        // row sum

__device__ __forceinline__ uint32_t f2tf32(float x) {
    uint32_t u;
    asm("cvt.rna.tf32.f32 %0, %1;" : "=r"(u) : "f"(x));
    return u;
}
__device__ __forceinline__ float ex2f(float x) {
    float y;
    asm("ex2.approx.ftz.f32 %0, %1;" : "=f"(y) : "f"(x));
    return y;
}
__device__ __forceinline__ void mma_tf32(float* c,
    uint32_t a0, uint32_t a1, uint32_t a2, uint32_t a3,
    uint32_t b0, uint32_t b1)
{
    asm volatile(
        "mma.sync.aligned.m16n8k8.row.col.f32.tf32.tf32.f32 "
        "{%0,%1,%2,%3}, {%4,%5,%6,%7}, {%8,%9}, {%0,%1,%2,%3};"
        : "+f"(c[0]), "+f"(c[1]), "+f"(c[2]), "+f"(c[3])
        : "r"(a0), "r"(a1), "r"(a2), "r"(a3), "r"(b0), "r"(b1));
}

// ---------------------------------------------------------------------------
// Fused projection. 384 threads = 12 warps. Warp group p = w/4 owns one
// projection (q/k/v); ww = w%4 owns a 16-row sub-tile of BM=64.
// BK=32, ping-pong staged (1 sync per iter). x loaded once.
// ---------------------------------------------------------------------------
#define XPAD 36
#define WPAD 68
#define PJ_BUF (64 * XPAD + 3 * 32 * WPAD)     // 8832 floats per stage buffer
#define PSMEM  (2 * PJ_BUF * 4)                // 70656 bytes

__device__ __forceinline__ void proj_stage(
    float* buf, const float* __restrict__ x,
    const float* const* Wp, int m0, int k0, int t)
{
    float* Xs = buf;
    float* Ws = buf + 64 * XPAD;
    // x tile [64][32]: 512 float4
    for (int idx = t; idx < 512; idx += 384) {
        int row = idx >> 3;
        int c4  = (idx & 7) << 2;
        float4 v = *(const float4*)(x + (size_t)(m0 + row) * Dc + k0 + c4);
        float* d = &Xs[row * XPAD + c4];
        d[0] = __uint_as_float(f2tf32(v.x));
        d[1] = __uint_as_float(f2tf32(v.y));
        d[2] = __uint_as_float(f2tf32(v.z));
        d[3] = __uint_as_float(f2tf32(v.w));
    }
    // W tiles 3x[32][64]: 1536 float4, 4 per thread
#pragma unroll
    for (int i = 0; i < 4; i++) {
        int idx = t + i * 384;
        int p   = idx >> 9;
        int rem = idx & 511;
        int row = rem >> 4;
        int c4  = (rem & 15) << 2;
        float4 v = *(const float4*)(Wp[p] + (size_t)(k0 + row) * Hc + c4);
        float* d = &Ws[p * 32 * WPAD + row * WPAD + c4];
        d[0] = __uint_as_float(f2tf32(v.x));
        d[1] = __uint_as_float(f2tf32(v.y));
        d[2] = __uint_as_float(f2tf32(v.z));
        d[3] = __uint_as_float(f2tf32(v.w));
    }
}

__global__ __launch_bounds__(384, 2) void proj_kernel(
    const float* __restrict__ x,
    const float* __restrict__ Wq, const float* __restrict__ Wk, const float* __restrict__ Wv,
    const float* __restrict__ bq, const float* __restrict__ bk, const float* __restrict__ bv)
{
    extern __shared__ float psm[];
    const float* Wp[3] = { Wq, Wk, Wv };

    const int t    = threadIdx.x;
    const int w    = t >> 5;
    const int p    = w >> 2;      // projection
    const int ww   = w & 3;       // row sub-tile
    const int lane = t & 31;
    const int g    = lane >> 2;
    const int q4   = lane & 3;
    const int m0   = blockIdx.x * 64;

    float acc[8][4];
#pragma unroll
    for (int nf = 0; nf < 8; nf++)
#pragma unroll
        for (int j = 0; j < 4; j++) acc[nf][j] = 0.f;

    proj_stage(psm, x, Wp, m0, 0, t);
    __syncthreads();

    for (int it = 0; it < 32; it++) {
        if (it + 1 < 32)
            proj_stage(psm + ((it + 1) & 1) * PJ_BUF, x, Wp, m0, (it + 1) * 32, t);

        const float* Xs = psm + (it & 1) * PJ_BUF;
        const float* Ws = Xs + 64 * XPAD + p * 32 * WPAD;
#pragma unroll
        for (int ks = 0; ks < 4; ks++) {
            const int kc = ks * 8 + q4;
            const int r  = ww * 16 + g;
            uint32_t a0 = __float_as_uint(Xs[(r    ) * XPAD + kc]);
            uint32_t a1 = __float_as_uint(Xs[(r + 8) * XPAD + kc]);
            uint32_t a2 = __float_as_uint(Xs[(r    ) * XPAD + kc + 4]);
            uint32_t a3 = __float_as_uint(Xs[(r + 8) * XPAD + kc + 4]);
#pragma unroll
            for (int nf = 0; nf < 8; nf++) {
                uint32_t b0 = __float_as_uint(Ws[(ks * 8 + q4    ) * WPAD + nf * 8 + g]);
                uint32_t b1 = __float_as_uint(Ws[(ks * 8 + q4 + 4) * WPAD + nf * 8 + g]);
                mma_tf32(acc[nf], a0, a1, a2, a3, b0, b1);
            }
        }
        __syncthreads();
    }

    const float* biases[3] = { bq, bk, bv };
    float* outs[3] = { g_q, g_k, g_v };
    float* out = outs[p];
    const float* bias = biases[p];
    const int r0 = m0 + ww * 16 + g;
#pragma unroll
    for (int nf = 0; nf < 8; nf++) {
        int col = nf * 8 + 2 * q4;
        float b0 = bias[col], b1 = bias[col + 1];
        float2 v0 = make_float2(acc[nf][0] + b0, acc[nf][1] + b1);
        float2 v1 = make_float2(acc[nf][2] + b0, acc[nf][3] + b1);
        *(float2*)(out + (size_t)r0 * Hc + col)       = v0;
        *(float2*)(out + (size_t)(r0 + 8) * Hc + col) = v1;
    }
}

// ---------------------------------------------------------------------------
// Attention partials: block = (batch, chunk-slot). 64 queries, 4 warps,
// processes <=8 KV tiles (64-wide), ping-pong staged. Writes (O, m, l).
// ---------------------------------------------------------------------------
#define KVPAD 68
#define TILEF (64 * KVPAD)
#define ASMEM ((4 * TILEF + 4 * 16 * KVPAD) * 4)   // 87040 bytes

__device__ __forceinline__ void attn_stage(
    float* Kbuf, float* Vbuf,
    const float* __restrict__ kb, const float* __restrict__ vb,
    int kn0, int t)
{
    const int row  = t & 63;
    const int half = (t >> 6) * 32;
    // K: [kv][h]
    {
        const float4* src = (const float4*)(kb + (size_t)(kn0 + row) * Hc + half);
        float* d = &Kbuf[row * KVPAD + half];
#pragma unroll
        for (int i = 0; i < 8; i++) {
            float4 v = src[i];
            d[i * 4 + 0] = __uint_as_float(f2tf32(v.x));
            d[i * 4 + 1] = __uint_as_float(f2tf32(v.y));
            d[i * 4 + 2] = __uint_as_float(f2tf32(v.z));
            d[i * 4 + 3] = __uint_as_float(f2tf32(v.w));
        }
    }
    // V transposed: [h][kv]
    {
        const float4* src = (const float4*)(vb + (size_t)(kn0 + row) * Hc + half);
#pragma unroll
        for (int i = 0; i < 8; i++) {
            float4 v = src[i];
            int h = half + i * 4;
            Vbuf[(h + 0) * KVPAD + row] = __uint_as_float(f2tf32(v.x));
            Vbuf[(h + 1) * KVPAD + row] = __uint_as_float(f2tf32(v.y));
            Vbuf[(h + 2) * KVPAD + row] = __uint_as_float(f2tf32(v.z));
            Vbuf[(h + 3) * KVPAD + row] = __uint_as_float(f2tf32(v.w));
        }
    }
}

__global__ __launch_bounds__(128) void attn_partial_kernel()
{
    extern __shared__ float sm[];
    float* Kb[2] = { sm, sm + TILEF };
    float* Vb[2] = { sm + 2 * TILEF, sm + 3 * TILEF };
    float* Psw   = sm + 4 * TILEF;

    const int b   = blockIdx.y;
    const int idx = (int)(gridDim.x - 1 - blockIdx.x);   // heavy chunks first

    // decode (qtile, chunk) from idx: group g has qtiles 8g..8g+7, g+1 chunks each
    int qt = 0, ch = 0;
#pragma unroll
    for (int gg = 3; gg >= 0; gg--) {
        int s = 4 * gg * (gg + 1);
        if (idx >= s) { qt = 8 * gg + (idx - s) / (gg + 1); ch = (idx - s) % (gg + 1); break; }
    }
    const int q0  = qt * 64;
    const int kt0 = ch * 8;
    const int kt1 = min(kt0 + 8, qt + 1);

    const int t    = threadIdx.x;
    const int w    = t >> 5;
    const int lane = t & 31;
    const int g    = lane >> 2;
    const int q4   = lane & 3;
    float* Pw = Psw + w * 16 * KVPAD;

    const float* qb = g_q + (size_t)b * Tc * Hc;
    const float* kb = g_k + (size_t)b * Tc * Hc;
    const float* vb = g_v + (size_t)b * Tc * Hc;

    const float SC = 0.125f * 1.44269504f;
    uint32_t qa[8][4];
    {
        const float* r0 = qb + (size_t)(q0 + w * 16 + g) * Hc;
        const float* r1 = r0 + 8 * Hc;
#pragma unroll
        for (int ks = 0; ks < 8; ks++) {
            qa[ks][0] = f2tf32(r0[ks * 8 + q4] * SC);
            qa[ks][1] = f2tf32(r1[ks * 8 + q4] * SC);
            qa[ks][2] = f2tf32(r0[ks * 8 + q4 + 4] * SC);
            qa[ks][3] = f2tf32(r1[ks * 8 + q4 + 4] * SC);
        }
    }

    float o[8][4];
#pragma unroll
    for (int nf = 0; nf < 8; nf++)
#pragma unroll
        for (int j = 0; j < 4; j++) o[nf][j] = 0.f;
    float m0 = -1e30f, m1 = -1e30f, l0 = 0.f, l1 = 0.f;

    attn_stage(Kb[0], Vb[0], kb, vb, kt0 * 64, t);
    __syncthreads();

    for (int kt = kt0; kt < kt1; kt++) {
        const int buf = (kt - kt0) & 1;
        if (kt + 1 < kt1)
            attn_stage(Kb[buf ^ 1], Vb[buf ^ 1], kb, vb, (kt + 1) * 64, t);

        const float* Ks = Kb[buf];
        const float* Vs = Vb[buf];
        const int kn0 = kt * 64;

        // S = Q @ K^T
        float sf[8][4];
#pragma unroll
        for (int nf = 0; nf < 8; nf++) {
            sf[nf][0] = sf[nf][1] = sf[nf][2] = sf[nf][3] = 0.f;
#pragma unroll
            for (int ks = 0; ks < 8; ks++) {
                uint32_t b0 = __float_as_uint(Ks[(nf * 8 + g) * KVPAD + ks * 8 + q4]);
                uint32_t b1 = __float_as_uint(Ks[(nf * 8 + g) * KVPAD + ks * 8 + q4 + 4]);
                mma_tf32(sf[nf], qa[ks][0], qa[ks][1], qa[ks][2], qa[ks][3], b0, b1);
            }
        }

        if (kt == qt) {   // diagonal tile: causal mask
            const int r0 = q0 + w * 16 + g;
            const int r1 = r0 + 8;
#pragma unroll
            for (int nf = 0; nf < 8; nf++) {
                int c0 = kn0 + nf * 8 + 2 * q4;
                if (c0     > r0) sf[nf][0] = -1e30f;
                if (c0 + 1 > r0) sf[nf][1] = -1e30f;
                if (c0     > r1) sf[nf][2] = -1e30f;
                if (c0 + 1 > r1) sf[nf][3] = -1e30f;
            }
        }

        // online softmax
        float mx0 = -1e30f, mx1 = -1e30f;
#pragma unroll
        for (int nf = 0; nf < 8; nf++) {
            mx0 = fmaxf(mx0, fmaxf(sf[nf][0], sf[nf][1]));
            mx1 = fmaxf(mx1, fmaxf(sf[nf][2], sf[nf][3]));
        }
        mx0 = fmaxf(mx0, __shfl_xor_sync(0xffffffffu, mx0, 1));
        mx0 = fmaxf(mx0, __shfl_xor_sync(0xffffffffu, mx0, 2));
        mx1 = fmaxf(mx1, __shfl_xor_sync(0xffffffffu, mx1, 1));
        mx1 = fmaxf(mx1, __shfl_xor_sync(0xffffffffu, mx1, 2));

        float mn0 = fmaxf(m0, mx0), mn1 = fmaxf(m1, mx1);
        float sc0 = ex2f(m0 - mn0), sc1 = ex2f(m1 - mn1);

        float rs0 = 0.f, rs1 = 0.f;
#pragma unroll
        for (int nf = 0; nf < 8; nf++) {
            sf[nf][0] = ex2f(sf[nf][0] - mn0);
            sf[nf][1] = ex2f(sf[nf][1] - mn0);
            sf[nf][2] = ex2f(sf[nf][2] - mn1);
            sf[nf][3] = ex2f(sf[nf][3] - mn1);
            rs0 += sf[nf][0] + sf[nf][1];
            rs1 += sf[nf][2] + sf[nf][3];
        }
        rs0 += __shfl_xor_sync(0xffffffffu, rs0, 1);
        rs0 += __shfl_xor_sync(0xffffffffu, rs0, 2);
        rs1 += __shfl_xor_sync(0xffffffffu, rs1, 1);
        rs1 += __shfl_xor_sync(0xffffffffu, rs1, 2);

        l0 = l0 * sc0 + rs0;  m0 = mn0;
        l1 = l1 * sc1 + rs1;  m1 = mn1;
#pragma unroll
        for (int nf = 0; nf < 8; nf++) {
            o[nf][0] *= sc0;  o[nf][1] *= sc0;
            o[nf][2] *= sc1;  o[nf][3] *= sc1;
        }

        // P -> warp-private smem
#pragma unroll
        for (int nf = 0; nf < 8; nf++) {
            int c = nf * 8 + 2 * q4;
            float2 p01 = make_float2(__uint_as_float(f2tf32(sf[nf][0])),
                                     __uint_as_float(f2tf32(sf[nf][1])));
            float2 p23 = make_float2(__uint_as_float(f2tf32(sf[nf][2])),
                                     __uint_as_float(f2tf32(sf[nf][3])));
            *(float2*)&Pw[(g    ) * KVPAD + c] = p01;
            *(float2*)&Pw[(g + 8) * KVPAD + c] = p23;
        }
        __syncwarp();

        // O += P @ V
#pragma unroll
        for (int ks = 0; ks < 8; ks++) {
            uint32_t a0 = __float_as_uint(Pw[(g    ) * KVPAD + ks * 8 + q4]);
            uint32_t a1 = __float_as_uint(Pw[(g + 8) * KVPAD + ks * 8 + q4]);
            uint32_t a2 = __float_as_uint(Pw[(g    ) * KVPAD + ks * 8 + q4 + 4]);
            uint32_t a3 = __float_as_uint(Pw[(g + 8) * KVPAD + ks * 8 + q4 + 4]);
#pragma unroll
            for (int nf = 0; nf < 8; nf++) {
                uint32_t b0 = __float_as_uint(Vs[(nf * 8 + g) * KVPAD + ks * 8 + q4]);
                uint32_t b1 = __float_as_uint(Vs[(nf * 8 + g) * KVPAD + ks * 8 + q4 + 4]);
                mma_tf32(o[nf], a0, a1, a2, a3, b0, b1);
            }
        }
        __syncthreads();
    }

    // write partial (unnormalized O, m, l)
    const int slot = b * SLOTS + idx;
    float* po = g_po + (size_t)slot * 4096;
    const int r0 = w * 16 + g;
    const int r1 = r0 + 8;
#pragma unroll
    for (int nf = 0; nf < 8; nf++) {
        int col = nf * 8 + 2 * q4;
        *(float2*)(po + r0 * 64 + col) = make_float2(o[nf][0], o[nf][1]);
        *(float2*)(po + r1 * 64 + col) = make_float2(o[nf][2], o[nf][3]);
    }
    if (q4 == 0) {
        g_pm[slot * 64 + r0] = m0;  g_pm[slot * 64 + r1] = m1;
        g_pl[slot * 64 + r0] = l0;  g_pl[slot * 64 + r1] = l1;
    }
}

// ---------------------------------------------------------------------------
// Merge: combine <=4 partials per query row. 32 threads per row, 8 rows/block.
// ---------------------------------------------------------------------------
__global__ __launch_bounds__(256) void merge_kernel(float* __restrict__ out)
{
    const int gid  = blockIdx.x * 8 + (threadIdx.x >> 5);   // row 0..16383
    const int lane = threadIdx.x & 31;
    const int b = gid >> 11;
    const int q = gid & 2047;
    const int qt    = q >> 6;
    const int rowin = q & 63;
    const int grp   = qt >> 3;
    const int nch   = grp + 1;
    const int base  = b * SLOTS + 4 * grp * (grp + 1) + (qt - 8 * grp) * (grp + 1);

    float mv[4];
    float M = -1e30f;
    for (int c = 0; c < nch; c++) {
        mv[c] = g_pm[(base + c) * 64 + rowin];
        M = fmaxf(M, mv[c]);
    }
    float L = 0.f, o0 = 0.f, o1 = 0.f;
    const int col = lane * 2;
    for (int c = 0; c < nch; c++) {
        float wgt = ex2f(mv[c] - M);
        L += wgt * g_pl[(base + c) * 64 + rowin];
        float2 ov = *(const float2*)(g_po + ((size_t)(base + c) * 64 + rowin) * 64 + col);
        o0 += wgt * ov.x;
        o1 += wgt * ov.y;
    }
    float inv = 1.f / L;
    *(float2*)(out + ((size_t)b * Tc + q) * Hc + col) = make_float2(o0 * inv, o1 * inv);
}

// ---------------------------------------------------------------------------
extern "C" void kernel_launch(void* const* d_in, const int* in_sizes, int n_in,
                              void* d_out, int out_size)
{
    (void)in_sizes; (void)n_in; (void)out_size;
    const float* x  = (const float*)d_in[0];
    const float* Wk = (const float*)d_in[1];
    const float* bk = (const float*)d_in[2];
    const float* Wq = (const float*)d_in[3];
    const float* bq = (const float*)d_in[4];
    const float* Wv = (const float*)d_in[5];
    const float* bv = (const float*)d_in[6];
    float* out = (float*)d_out;

    cudaFuncSetAttribute(proj_kernel, cudaFuncAttributeMaxDynamicSharedMemorySize, PSMEM);
    cudaFuncSetAttribute(attn_partial_kernel, cudaFuncAttributeMaxDynamicSharedMemorySize, ASMEM);

    proj_kernel<<<(Bc * Tc) / 64, 384, PSMEM>>>(x, Wq, Wk, Wv, bq, bk, bv);

    dim3 ag(SLOTS, Bc);
    attn_partial_kernel<<<ag, 128, ASMEM>>>();

    merge_kernel<<<(Bc * Tc) / 8, 256>>>(out);
}

// round 6
// speedup vs baseline: 2.4300x; 1.0152x over previous
#include <cuda_runtime.h>
#include <cuda_bf16.h>
#include <cstdint>

constexpr int Bc = 8;
constexpr int Tc = 2048;
constexpr int Dc = 1024;
constexpr int Hc = 64;

// q/k/v projections
__device__ float g_q[Bc * Tc * Hc];
__device__ float g_k[Bc * Tc * Hc];
__device__ float g_v[Bc * Tc * Hc];

// split-KV partials: 80 chunk-slots per batch (qtile i has ceil((i+1)/8) chunks)
constexpr int SLOTS = 80;
__device__ float g_po[Bc * SLOTS * 64 * 64];   // unnormalized O
__device__ float g_pm[Bc * SLOTS * 64];        // row max (exp2 space)
__device__ float g_pl[Bc * SLOTS * 64];        // row sum

__device__ __forceinline__ uint32_t f2tf32(float x) {
    uint32_t u;
    asm("cvt.rna.tf32.f32 %0, %1;" : "=r"(u) : "f"(x));
    return u;
}
__device__ __forceinline__ float ex2f(float x) {
    float y;
    asm("ex2.approx.ftz.f32 %0, %1;" : "=f"(y) : "f"(x));
    return y;
}
__device__ __forceinline__ void mma_tf32(float* c,
    uint32_t a0, uint32_t a1, uint32_t a2, uint32_t a3,
    uint32_t b0, uint32_t b1)
{
    asm volatile(
        "mma.sync.aligned.m16n8k8.row.col.f32.tf32.tf32.f32 "
        "{%0,%1,%2,%3}, {%4,%5,%6,%7}, {%8,%9}, {%0,%1,%2,%3};"
        : "+f"(c[0]), "+f"(c[1]), "+f"(c[2]), "+f"(c[3])
        : "r"(a0), "r"(a1), "r"(a2), "r"(a3), "r"(b0), "r"(b1));
}

// ---------------------------------------------------------------------------
// Fused projection. 384 threads = 12 warps. Warp group p = w/4 owns one
// projection (q/k/v); ww = w%4 owns a 16-row sub-tile of BM=64.
// BK=32, ping-pong staged (1 sync per iter). x loaded once.
// ---------------------------------------------------------------------------
#define XPAD 36
#define WPAD 68
#define PJ_BUF (64 * XPAD + 3 * 32 * WPAD)     // 8832 floats per stage buffer
#define PSMEM  (2 * PJ_BUF * 4)                // 70656 bytes

__device__ __forceinline__ void proj_stage(
    float* buf, const float* __restrict__ x,
    const float* const* Wp, int m0, int k0, int t)
{
    float* Xs = buf;
    float* Ws = buf + 64 * XPAD;
    // x tile [64][32]: 512 float4
    for (int idx = t; idx < 512; idx += 384) {
        int row = idx >> 3;
        int c4  = (idx & 7) << 2;
        float4 v = *(const float4*)(x + (size_t)(m0 + row) * Dc + k0 + c4);
        float* d = &Xs[row * XPAD + c4];
        d[0] = __uint_as_float(f2tf32(v.x));
        d[1] = __uint_as_float(f2tf32(v.y));
        d[2] = __uint_as_float(f2tf32(v.z));
        d[3] = __uint_as_float(f2tf32(v.w));
    }
    // W tiles 3x[32][64]: 1536 float4, 4 per thread
#pragma unroll
    for (int i = 0; i < 4; i++) {
        int idx = t + i * 384;
        int p   = idx >> 9;
        int rem = idx & 511;
        int row = rem >> 4;
        int c4  = (rem & 15) << 2;
        float4 v = *(const float4*)(Wp[p] + (size_t)(k0 + row) * Hc + c4);
        float* d = &Ws[p * 32 * WPAD + row * WPAD + c4];
        d[0] = __uint_as_float(f2tf32(v.x));
        d[1] = __uint_as_float(f2tf32(v.y));
        d[2] = __uint_as_float(f2tf32(v.z));
        d[3] = __uint_as_float(f2tf32(v.w));
    }
}

__global__ __launch_bounds__(384, 2) void proj_kernel(
    const float* __restrict__ x,
    const float* __restrict__ Wq, const float* __restrict__ Wk, const float* __restrict__ Wv,
    const float* __restrict__ bq, const float* __restrict__ bk, const float* __restrict__ bv)
{
    extern __shared__ float psm[];
    const float* Wp[3] = { Wq, Wk, Wv };

    const int t    = threadIdx.x;
    const int w    = t >> 5;
    const int p    = w >> 2;      // projection
    const int ww   = w & 3;       // row sub-tile
    const int lane = t & 31;
    const int g    = lane >> 2;
    const int q4   = lane & 3;
    const int m0   = blockIdx.x * 64;

    float acc[8][4];
#pragma unroll
    for (int nf = 0; nf < 8; nf++)
#pragma unroll
        for (int j = 0; j < 4; j++) acc[nf][j] = 0.f;

    proj_stage(psm, x, Wp, m0, 0, t);
    __syncthreads();

    for (int it = 0; it < 32; it++) {
        if (it + 1 < 32)
            proj_stage(psm + ((it + 1) & 1) * PJ_BUF, x, Wp, m0, (it + 1) * 32, t);

        const float* Xs = psm + (it & 1) * PJ_BUF;
        const float* Ws = Xs + 64 * XPAD + p * 32 * WPAD;
#pragma unroll
        for (int ks = 0; ks < 4; ks++) {
            const int kc = ks * 8 + q4;
            const int r  = ww * 16 + g;
            uint32_t a0 = __float_as_uint(Xs[(r    ) * XPAD + kc]);
            uint32_t a1 = __float_as_uint(Xs[(r + 8) * XPAD + kc]);
            uint32_t a2 = __float_as_uint(Xs[(r    ) * XPAD + kc + 4]);
            uint32_t a3 = __float_as_uint(Xs[(r + 8) * XPAD + kc + 4]);
#pragma unroll
            for (int nf = 0; nf < 8; nf++) {
                uint32_t b0 = __float_as_uint(Ws[(ks * 8 + q4    ) * WPAD + nf * 8 + g]);
                uint32_t b1 = __float_as_uint(Ws[(ks * 8 + q4 + 4) * WPAD + nf * 8 + g]);
                mma_tf32(acc[nf], a0, a1, a2, a3, b0, b1);
            }
        }
        __syncthreads();
    }

    const float* biases[3] = { bq, bk, bv };
    float* outs[3] = { g_q, g_k, g_v };
    float* out = outs[p];
    const float* bias = biases[p];
    const int r0 = m0 + ww * 16 + g;
#pragma unroll
    for (int nf = 0; nf < 8; nf++) {
        int col = nf * 8 + 2 * q4;
        float b0 = bias[col], b1 = bias[col + 1];
        float2 v0 = make_float2(acc[nf][0] + b0, acc[nf][1] + b1);
        float2 v1 = make_float2(acc[nf][2] + b0, acc[nf][3] + b1);
        *(float2*)(out + (size_t)r0 * Hc + col)       = v0;
        *(float2*)(out + (size_t)(r0 + 8) * Hc + col) = v1;
    }
}

// ---------------------------------------------------------------------------
// Attention partials: block = (batch, chunk-slot). 64 queries, 4 warps,
// processes <=8 KV tiles (64-wide), ping-pong staged. Writes (O, m, l).
// ---------------------------------------------------------------------------
#define KVPAD 68
#define TILEF (64 * KVPAD)
#define ASMEM ((4 * TILEF + 4 * 16 * KVPAD) * 4)   // 87040 bytes

__device__ __forceinline__ void attn_stage(
    float* Kbuf, float* Vbuf,
    const float* __restrict__ kb, const float* __restrict__ vb,
    int kn0, int t)
{
    const int row  = t & 63;
    const int half = (t >> 6) * 32;
    // K: [kv][h]
    {
        const float4* src = (const float4*)(kb + (size_t)(kn0 + row) * Hc + half);
        float* d = &Kbuf[row * KVPAD + half];
#pragma unroll
        for (int i = 0; i < 8; i++) {
            float4 v = src[i];
            d[i * 4 + 0] = __uint_as_float(f2tf32(v.x));
            d[i * 4 + 1] = __uint_as_float(f2tf32(v.y));
            d[i * 4 + 2] = __uint_as_float(f2tf32(v.z));
            d[i * 4 + 3] = __uint_as_float(f2tf32(v.w));
        }
    }
    // V transposed: [h][kv]
    {
        const float4* src = (const float4*)(vb + (size_t)(kn0 + row) * Hc + half);
#pragma unroll
        for (int i = 0; i < 8; i++) {
            float4 v = src[i];
            int h = half + i * 4;
            Vbuf[(h + 0) * KVPAD + row] = __uint_as_float(f2tf32(v.x));
            Vbuf[(h + 1) * KVPAD + row] = __uint_as_float(f2tf32(v.y));
            Vbuf[(h + 2) * KVPAD + row] = __uint_as_float(f2tf32(v.z));
            Vbuf[(h + 3) * KVPAD + row] = __uint_as_float(f2tf32(v.w));
        }
    }
}

__global__ __launch_bounds__(128) void attn_partial_kernel()
{
    extern __shared__ float sm[];
    float* Kb[2] = { sm, sm + TILEF };
    float* Vb[2] = { sm + 2 * TILEF, sm + 3 * TILEF };
    float* Psw   = sm + 4 * TILEF;

    const int b   = blockIdx.y;
    const int idx = (int)(gridDim.x - 1 - blockIdx.x);   // heavy chunks first

    // decode (qtile, chunk) from idx: group g has qtiles 8g..8g+7, g+1 chunks each
    int qt = 0, ch = 0;
#pragma unroll
    for (int gg = 3; gg >= 0; gg--) {
        int s = 4 * gg * (gg + 1);
        if (idx >= s) { qt = 8 * gg + (idx - s) / (gg + 1); ch = (idx - s) % (gg + 1); break; }
    }
    const int q0  = qt * 64;
    const int kt0 = ch * 8;
    const int kt1 = min(kt0 + 8, qt + 1);

    const int t    = threadIdx.x;
    const int w    = t >> 5;
    const int lane = t & 31;
    const int g    = lane >> 2;
    const int q4   = lane & 3;
    float* Pw = Psw + w * 16 * KVPAD;

    const float* qb = g_q + (size_t)b * Tc * Hc;
    const float* kb = g_k + (size_t)b * Tc * Hc;
    const float* vb = g_v + (size_t)b * Tc * Hc;

    const float SC = 0.125f * 1.44269504f;
    uint32_t qa[8][4];
    {
        const float* r0 = qb + (size_t)(q0 + w * 16 + g) * Hc;
        const float* r1 = r0 + 8 * Hc;
#pragma unroll
        for (int ks = 0; ks < 8; ks++) {
            qa[ks][0] = f2tf32(r0[ks * 8 + q4] * SC);
            qa[ks][1] = f2tf32(r1[ks * 8 + q4] * SC);
            qa[ks][2] = f2tf32(r0[ks * 8 + q4 + 4] * SC);
            qa[ks][3] = f2tf32(r1[ks * 8 + q4 + 4] * SC);
        }
    }

    float o[8][4];
#pragma unroll
    for (int nf = 0; nf < 8; nf++)
#pragma unroll
        for (int j = 0; j < 4; j++) o[nf][j] = 0.f;
    float m0 = -1e30f, m1 = -1e30f, l0 = 0.f, l1 = 0.f;

    attn_stage(Kb[0], Vb[0], kb, vb, kt0 * 64, t);
    __syncthreads();

    for (int kt = kt0; kt < kt1; kt++) {
        const int buf = (kt - kt0) & 1;
        if (kt + 1 < kt1)
            attn_stage(Kb[buf ^ 1], Vb[buf ^ 1], kb, vb, (kt + 1) * 64, t);

        const float* Ks = Kb[buf];
        const float* Vs = Vb[buf];
        const int kn0 = kt * 64;

        // S = Q @ K^T
        float sf[8][4];
#pragma unroll
        for (int nf = 0; nf < 8; nf++) {
            sf[nf][0] = sf[nf][1] = sf[nf][2] = sf[nf][3] = 0.f;
#pragma unroll
            for (int ks = 0; ks < 8; ks++) {
                uint32_t b0 = __float_as_uint(Ks[(nf * 8 + g) * KVPAD + ks * 8 + q4]);
                uint32_t b1 = __float_as_uint(Ks[(nf * 8 + g) * KVPAD + ks * 8 + q4 + 4]);
                mma_tf32(sf[nf], qa[ks][0], qa[ks][1], qa[ks][2], qa[ks][3], b0, b1);
            }
        }

        if (kt == qt) {   // diagonal tile: causal mask
            const int r0 = q0 + w * 16 + g;
            const int r1 = r0 + 8;
#pragma unroll
            for (int nf = 0; nf < 8; nf++) {
                int c0 = kn0 + nf * 8 + 2 * q4;
                if (c0     > r0) sf[nf][0] = -1e30f;
                if (c0 + 1 > r0) sf[nf][1] = -1e30f;
                if (c0     > r1) sf[nf][2] = -1e30f;
                if (c0 + 1 > r1) sf[nf][3] = -1e30f;
            }
        }

        // online softmax
        float mx0 = -1e30f, mx1 = -1e30f;
#pragma unroll
        for (int nf = 0; nf < 8; nf++) {
            mx0 = fmaxf(mx0, fmaxf(sf[nf][0], sf[nf][1]));
            mx1 = fmaxf(mx1, fmaxf(sf[nf][2], sf[nf][3]));
        }
        mx0 = fmaxf(mx0, __shfl_xor_sync(0xffffffffu, mx0, 1));
        mx0 = fmaxf(mx0, __shfl_xor_sync(0xffffffffu, mx0, 2));
        mx1 = fmaxf(mx1, __shfl_xor_sync(0xffffffffu, mx1, 1));
        mx1 = fmaxf(mx1, __shfl_xor_sync(0xffffffffu, mx1, 2));

        float mn0 = fmaxf(m0, mx0), mn1 = fmaxf(m1, mx1);
        float sc0 = ex2f(m0 - mn0), sc1 = ex2f(m1 - mn1);

        float rs0 = 0.f, rs1 = 0.f;
#pragma unroll
        for (int nf = 0; nf < 8; nf++) {
            sf[nf][0] = ex2f(sf[nf][0] - mn0);
            sf[nf][1] = ex2f(sf[nf][1] - mn0);
            sf[nf][2] = ex2f(sf[nf][2] - mn1);
            sf[nf][3] = ex2f(sf[nf][3] - mn1);
            rs0 += sf[nf][0] + sf[nf][1];
            rs1 += sf[nf][2] + sf[nf][3];
        }
        rs0 += __shfl_xor_sync(0xffffffffu, rs0, 1);
        rs0 += __shfl_xor_sync(0xffffffffu, rs0, 2);
        rs1 += __shfl_xor_sync(0xffffffffu, rs1, 1);
        rs1 += __shfl_xor_sync(0xffffffffu, rs1, 2);

        l0 = l0 * sc0 + rs0;  m0 = mn0;
        l1 = l1 * sc1 + rs1;  m1 = mn1;
#pragma unroll
        for (int nf = 0; nf < 8; nf++) {
            o[nf][0] *= sc0;  o[nf][1] *= sc0;
            o[nf][2] *= sc1;  o[nf][3] *= sc1;
        }

        // P -> warp-private smem
#pragma unroll
        for (int nf = 0; nf < 8; nf++) {
            int c = nf * 8 + 2 * q4;
            float2 p01 = make_float2(__uint_as_float(f2tf32(sf[nf][0])),
                                     __uint_as_float(f2tf32(sf[nf][1])));
            float2 p23 = make_float2(__uint_as_float(f2tf32(sf[nf][2])),
                                     __uint_as_float(f2tf32(sf[nf][3])));
            *(float2*)&Pw[(g    ) * KVPAD + c] = p01;
            *(float2*)&Pw[(g + 8) * KVPAD + c] = p23;
        }
        __syncwarp();

        // O += P @ V
#pragma unroll
        for (int ks = 0; ks < 8; ks++) {
            uint32_t a0 = __float_as_uint(Pw[(g    ) * KVPAD + ks * 8 + q4]);
            uint32_t a1 = __float_as_uint(Pw[(g + 8) * KVPAD + ks * 8 + q4]);
            uint32_t a2 = __float_as_uint(Pw[(g    ) * KVPAD + ks * 8 + q4 + 4]);
            uint32_t a3 = __float_as_uint(Pw[(g + 8) * KVPAD + ks * 8 + q4 + 4]);
#pragma unroll
            for (int nf = 0; nf < 8; nf++) {
                uint32_t b0 = __float_as_uint(Vs[(nf * 8 + g) * KVPAD + ks * 8 + q4]);
                uint32_t b1 = __float_as_uint(Vs[(nf * 8 + g) * KVPAD + ks * 8 + q4 + 4]);
                mma_tf32(o[nf], a0, a1, a2, a3, b0, b1);
            }
        }
        __syncthreads();
    }

    // write partial (unnormalized O, m, l)
    const int slot = b * SLOTS + idx;
    float* po = g_po + (size_t)slot * 4096;
    const int r0 = w * 16 + g;
    const int r1 = r0 + 8;
#pragma unroll
    for (int nf = 0; nf < 8; nf++) {
        int col = nf * 8 + 2 * q4;
        *(float2*)(po + r0 * 64 + col) = make_float2(o[nf][0], o[nf][1]);
        *(float2*)(po + r1 * 64 + col) = make_float2(o[nf][2], o[nf][3]);
    }
    if (q4 == 0) {
        g_pm[slot * 64 + r0] = m0;  g_pm[slot * 64 + r1] = m1;
        g_pl[slot * 64 + r0] = l0;  g_pl[slot * 64 + r1] = l1;
    }
}

// ---------------------------------------------------------------------------
// Merge: combine <=4 partials per query row. 32 threads per row, 8 rows/block.
// ---------------------------------------------------------------------------
__global__ __launch_bounds__(256) void merge_kernel(float* __restrict__ out)
{
    const int gid  = blockIdx.x * 8 + (threadIdx.x >> 5);   // row 0..16383
    const int lane = threadIdx.x & 31;
    const int b = gid >> 11;
    const int q = gid & 2047;
    const int qt    = q >> 6;
    const int rowin = q & 63;
    const int grp   = qt >> 3;
    const int nch   = grp + 1;
    const int base  = b * SLOTS + 4 * grp * (grp + 1) + (qt - 8 * grp) * (grp + 1);

    float mv[4];
    float M = -1e30f;
    for (int c = 0; c < nch; c++) {
        mv[c] = g_pm[(base + c) * 64 + rowin];
        M = fmaxf(M, mv[c]);
    }
    float L = 0.f, o0 = 0.f, o1 = 0.f;
    const int col = lane * 2;
    for (int c = 0; c < nch; c++) {
        float wgt = ex2f(mv[c] - M);
        L += wgt * g_pl[(base + c) * 64 + rowin];
        float2 ov = *(const float2*)(g_po + ((size_t)(base + c) * 64 + rowin) * 64 + col);
        o0 += wgt * ov.x;
        o1 += wgt * ov.y;
    }
    float inv = 1.f / L;
    *(float2*)(out + ((size_t)b * Tc + q) * Hc + col) = make_float2(o0 * inv, o1 * inv);
}

// ---------------------------------------------------------------------------
extern "C" void kernel_launch(void* const* d_in, const int* in_sizes, int n_in,
                              void* d_out, int out_size)
{
    (void)in_sizes; (void)n_in; (void)out_size;
    const float* x  = (const float*)d_in[0];
    const float* Wk = (const float*)d_in[1];
    const float* bk = (const float*)d_in[2];
    const float* Wq = (const float*)d_in[3];
    const float* bq = (const float*)d_in[4];
    const float* Wv = (const float*)d_in[5];
    const float* bv = (const float*)d_in[6];
    float* out = (float*)d_out;

    cudaFuncSetAttribute(proj_kernel, cudaFuncAttributeMaxDynamicSharedMemorySize, PSMEM);
    cudaFuncSetAttribute(attn_partial_kernel, cudaFuncAttributeMaxDynamicSharedMemorySize, ASMEM);

    proj_kernel<<<(Bc * Tc) / 64, 384, PSMEM>>>(x, Wq, Wk, Wv, bq, bk, bv);

    dim3 ag(SLOTS, Bc);
    attn_partial_kernel<<<ag, 128, ASMEM>>>();

    merge_kernel<<<(Bc * Tc) / 8, 256>>>(out);
}

// round 7
// speedup vs baseline: 2.4369x; 1.0028x over previous
#include <cuda_runtime.h>
#include <cuda_bf16.h>
#include <cstdint>

constexpr int Bc = 8;
constexpr int Tc = 2048;
constexpr int Dc = 1024;
constexpr int Hc = 64;

// q/k/v projections
__device__ float g_q[Bc * Tc * Hc];
__device__ float g_k[Bc * Tc * Hc];
__device__ float g_v[Bc * Tc * Hc];

// split-KV partials: 80 chunk-slots per batch (qtile i has ceil((i+1)/8) chunks)
constexpr int SLOTS = 80;
__device__ float g_po[Bc * SLOTS * 64 * 64];   // unnormalized O
__device__ float g_pm[Bc * SLOTS * 64];        // row max (exp2 space)
__device__ float g_pl[Bc * SLOTS * 64];        // row sum

__device__ __forceinline__ uint32_t f2tf32(float x) {
    uint32_t u;
    asm("cvt.rna.tf32.f32 %0, %1;" : "=r"(u) : "f"(x));
    return u;
}
__device__ __forceinline__ float ex2f(float x) {
    float y;
    asm("ex2.approx.ftz.f32 %0, %1;" : "=f"(y) : "f"(x));
    return y;
}
__device__ __forceinline__ void mma_tf32(float* c,
    uint32_t a0, uint32_t a1, uint32_t a2, uint32_t a3,
    uint32_t b0, uint32_t b1)
{
    asm volatile(
        "mma.sync.aligned.m16n8k8.row.col.f32.tf32.tf32.f32 "
        "{%0,%1,%2,%3}, {%4,%5,%6,%7}, {%8,%9}, {%0,%1,%2,%3};"
        : "+f"(c[0]), "+f"(c[1]), "+f"(c[2]), "+f"(c[3])
        : "r"(a0), "r"(a1), "r"(a2), "r"(a3), "r"(b0), "r"(b1));
}

// ---------------------------------------------------------------------------
// Fused projection. 384 threads = 12 warps. Warp group p = w/4 owns one
// projection (q/k/v); ww = w%4 owns a 16-row sub-tile of BM=64.
// BK=32, ping-pong staged (1 sync per iter). x loaded once.
// ---------------------------------------------------------------------------
#define XPAD 36
#define WPAD 68
#define PJ_BUF (64 * XPAD + 3 * 32 * WPAD)     // 8832 floats per stage buffer
#define PSMEM  (2 * PJ_BUF * 4)                // 70656 bytes

__device__ __forceinline__ void proj_stage(
    float* buf, const float* __restrict__ x,
    const float* const* Wp, int m0, int k0, int t)
{
    float* Xs = buf;
    float* Ws = buf + 64 * XPAD;
    // x tile [64][32]: 512 float4
    for (int idx = t; idx < 512; idx += 384) {
        int row = idx >> 3;
        int c4  = (idx & 7) << 2;
        float4 v = *(const float4*)(x + (size_t)(m0 + row) * Dc + k0 + c4);
        float* d = &Xs[row * XPAD + c4];
        d[0] = __uint_as_float(f2tf32(v.x));
        d[1] = __uint_as_float(f2tf32(v.y));
        d[2] = __uint_as_float(f2tf32(v.z));
        d[3] = __uint_as_float(f2tf32(v.w));
    }
    // W tiles 3x[32][64]: 1536 float4, 4 per thread
#pragma unroll
    for (int i = 0; i < 4; i++) {
        int idx = t + i * 384;
        int p   = idx >> 9;
        int rem = idx & 511;
        int row = rem >> 4;
        int c4  = (rem & 15) << 2;
        float4 v = *(const float4*)(Wp[p] + (size_t)(k0 + row) * Hc + c4);
        float* d = &Ws[p * 32 * WPAD + row * WPAD + c4];
        d[0] = __uint_as_float(f2tf32(v.x));
        d[1] = __uint_as_float(f2tf32(v.y));
        d[2] = __uint_as_float(f2tf32(v.z));
        d[3] = __uint_as_float(f2tf32(v.w));
    }
}

__global__ __launch_bounds__(384, 2) void proj_kernel(
    const float* __restrict__ x,
    const float* __restrict__ Wq, const float* __restrict__ Wk, const float* __restrict__ Wv,
    const float* __restrict__ bq, const float* __restrict__ bk, const float* __restrict__ bv)
{
    extern __shared__ float psm[];
    const float* Wp[3] = { Wq, Wk, Wv };

    const int t    = threadIdx.x;
    const int w    = t >> 5;
    const int p    = w >> 2;      // projection
    const int ww   = w & 3;       // row sub-tile
    const int lane = t & 31;
    const int g    = lane >> 2;
    const int q4   = lane & 3;
    const int m0   = blockIdx.x * 64;

    float acc[8][4];
#pragma unroll
    for (int nf = 0; nf < 8; nf++)
#pragma unroll
        for (int j = 0; j < 4; j++) acc[nf][j] = 0.f;

    proj_stage(psm, x, Wp, m0, 0, t);
    __syncthreads();

    for (int it = 0; it < 32; it++) {
        if (it + 1 < 32)
            proj_stage(psm + ((it + 1) & 1) * PJ_BUF, x, Wp, m0, (it + 1) * 32, t);

        const float* Xs = psm + (it & 1) * PJ_BUF;
        const float* Ws = Xs + 64 * XPAD + p * 32 * WPAD;
#pragma unroll
        for (int ks = 0; ks < 4; ks++) {
            const int kc = ks * 8 + q4;
            const int r  = ww * 16 + g;
            uint32_t a0 = __float_as_uint(Xs[(r    ) * XPAD + kc]);
            uint32_t a1 = __float_as_uint(Xs[(r + 8) * XPAD + kc]);
            uint32_t a2 = __float_as_uint(Xs[(r    ) * XPAD + kc + 4]);
            uint32_t a3 = __float_as_uint(Xs[(r + 8) * XPAD + kc + 4]);
#pragma unroll
            for (int nf = 0; nf < 8; nf++) {
                uint32_t b0 = __float_as_uint(Ws[(ks * 8 + q4    ) * WPAD + nf * 8 + g]);
                uint32_t b1 = __float_as_uint(Ws[(ks * 8 + q4 + 4) * WPAD + nf * 8 + g]);
                mma_tf32(acc[nf], a0, a1, a2, a3, b0, b1);
            }
        }
        __syncthreads();
    }

    const float* biases[3] = { bq, bk, bv };
    float* outs[3] = { g_q, g_k, g_v };
    float* out = outs[p];
    const float* bias = biases[p];
    const int r0 = m0 + ww * 16 + g;
#pragma unroll
    for (int nf = 0; nf < 8; nf++) {
        int col = nf * 8 + 2 * q4;
        float b0 = bias[col], b1 = bias[col + 1];
        float2 v0 = make_float2(acc[nf][0] + b0, acc[nf][1] + b1);
        float2 v1 = make_float2(acc[nf][2] + b0, acc[nf][3] + b1);
        *(float2*)(out + (size_t)r0 * Hc + col)       = v0;
        *(float2*)(out + (size_t)(r0 + 8) * Hc + col) = v1;
    }
}

// ---------------------------------------------------------------------------
// Attention partials: block = (batch, chunk-slot). 64 queries, 4 warps,
// processes <=8 KV tiles (64-wide), ping-pong staged. Writes (O, m, l).
// ---------------------------------------------------------------------------
#define KVPAD 68
#define TILEF (64 * KVPAD)
#define ASMEM ((4 * TILEF + 4 * 16 * KVPAD) * 4)   // 87040 bytes

__device__ __forceinline__ void attn_stage(
    float* Kbuf, float* Vbuf,
    const float* __restrict__ kb, const float* __restrict__ vb,
    int kn0, int t)
{
    const int row  = t & 63;
    const int half = (t >> 6) * 32;
    // K: [kv][h]
    {
        const float4* src = (const float4*)(kb + (size_t)(kn0 + row) * Hc + half);
        float* d = &Kbuf[row * KVPAD + half];
#pragma unroll
        for (int i = 0; i < 8; i++) {
            float4 v = src[i];
            d[i * 4 + 0] = __uint_as_float(f2tf32(v.x));
            d[i * 4 + 1] = __uint_as_float(f2tf32(v.y));
            d[i * 4 + 2] = __uint_as_float(f2tf32(v.z));
            d[i * 4 + 3] = __uint_as_float(f2tf32(v.w));
        }
    }
    // V transposed: [h][kv]
    {
        const float4* src = (const float4*)(vb + (size_t)(kn0 + row) * Hc + half);
#pragma unroll
        for (int i = 0; i < 8; i++) {
            float4 v = src[i];
            int h = half + i * 4;
            Vbuf[(h + 0) * KVPAD + row] = __uint_as_float(f2tf32(v.x));
            Vbuf[(h + 1) * KVPAD + row] = __uint_as_float(f2tf32(v.y));
            Vbuf[(h + 2) * KVPAD + row] = __uint_as_float(f2tf32(v.z));
            Vbuf[(h + 3) * KVPAD + row] = __uint_as_float(f2tf32(v.w));
        }
    }
}

__global__ __launch_bounds__(128) void attn_partial_kernel()
{
    extern __shared__ float sm[];
    float* Kb[2] = { sm, sm + TILEF };
    float* Vb[2] = { sm + 2 * TILEF, sm + 3 * TILEF };
    float* Psw   = sm + 4 * TILEF;

    const int b   = blockIdx.y;
    const int idx = (int)(gridDim.x - 1 - blockIdx.x);   // heavy chunks first

    // decode (qtile, chunk) from idx: group g has qtiles 8g..8g+7, g+1 chunks each
    int qt = 0, ch = 0;
#pragma unroll
    for (int gg = 3; gg >= 0; gg--) {
        int s = 4 * gg * (gg + 1);
        if (idx >= s) { qt = 8 * gg + (idx - s) / (gg + 1); ch = (idx - s) % (gg + 1); break; }
    }
    const int q0  = qt * 64;
    const int kt0 = ch * 8;
    const int kt1 = min(kt0 + 8, qt + 1);

    const int t    = threadIdx.x;
    const int w    = t >> 5;
    const int lane = t & 31;
    const int g    = lane >> 2;
    const int q4   = lane & 3;
    float* Pw = Psw + w * 16 * KVPAD;

    const float* qb = g_q + (size_t)b * Tc * Hc;
    const float* kb = g_k + (size_t)b * Tc * Hc;
    const float* vb = g_v + (size_t)b * Tc * Hc;

    const float SC = 0.125f * 1.44269504f;
    uint32_t qa[8][4];
    {
        const float* r0 = qb + (size_t)(q0 + w * 16 + g) * Hc;
        const float* r1 = r0 + 8 * Hc;
#pragma unroll
        for (int ks = 0; ks < 8; ks++) {
            qa[ks][0] = f2tf32(r0[ks * 8 + q4] * SC);
            qa[ks][1] = f2tf32(r1[ks * 8 + q4] * SC);
            qa[ks][2] = f2tf32(r0[ks * 8 + q4 + 4] * SC);
            qa[ks][3] = f2tf32(r1[ks * 8 + q4 + 4] * SC);
        }
    }

    float o[8][4];
#pragma unroll
    for (int nf = 0; nf < 8; nf++)
#pragma unroll
        for (int j = 0; j < 4; j++) o[nf][j] = 0.f;
    float m0 = -1e30f, m1 = -1e30f, l0 = 0.f, l1 = 0.f;

    attn_stage(Kb[0], Vb[0], kb, vb, kt0 * 64, t);
    __syncthreads();

    for (int kt = kt0; kt < kt1; kt++) {
        const int buf = (kt - kt0) & 1;
        if (kt + 1 < kt1)
            attn_stage(Kb[buf ^ 1], Vb[buf ^ 1], kb, vb, (kt + 1) * 64, t);

        const float* Ks = Kb[buf];
        const float* Vs = Vb[buf];
        const int kn0 = kt * 64;

        // S = Q @ K^T
        float sf[8][4];
#pragma unroll
        for (int nf = 0; nf < 8; nf++) {
            sf[nf][0] = sf[nf][1] = sf[nf][2] = sf[nf][3] = 0.f;
#pragma unroll
            for (int ks = 0; ks < 8; ks++) {
                uint32_t b0 = __float_as_uint(Ks[(nf * 8 + g) * KVPAD + ks * 8 + q4]);
                uint32_t b1 = __float_as_uint(Ks[(nf * 8 + g) * KVPAD + ks * 8 + q4 + 4]);
                mma_tf32(sf[nf], qa[ks][0], qa[ks][1], qa[ks][2], qa[ks][3], b0, b1);
            }
        }

        if (kt == qt) {   // diagonal tile: causal mask
            const int r0 = q0 + w * 16 + g;
            const int r1 = r0 + 8;
#pragma unroll
            for (int nf = 0; nf < 8; nf++) {
                int c0 = kn0 + nf * 8 + 2 * q4;
                if (c0     > r0) sf[nf][0] = -1e30f;
                if (c0 + 1 > r0) sf[nf][1] = -1e30f;
                if (c0     > r1) sf[nf][2] = -1e30f;
                if (c0 + 1 > r1) sf[nf][3] = -1e30f;
            }
        }

        // online softmax
        float mx0 = -1e30f, mx1 = -1e30f;
#pragma unroll
        for (int nf = 0; nf < 8; nf++) {
            mx0 = fmaxf(mx0, fmaxf(sf[nf][0], sf[nf][1]));
            mx1 = fmaxf(mx1, fmaxf(sf[nf][2], sf[nf][3]));
        }
        mx0 = fmaxf(mx0, __shfl_xor_sync(0xffffffffu, mx0, 1));
        mx0 = fmaxf(mx0, __shfl_xor_sync(0xffffffffu, mx0, 2));
        mx1 = fmaxf(mx1, __shfl_xor_sync(0xffffffffu, mx1, 1));
        mx1 = fmaxf(mx1, __shfl_xor_sync(0xffffffffu, mx1, 2));

        float mn0 = fmaxf(m0, mx0), mn1 = fmaxf(m1, mx1);
        float sc0 = ex2f(m0 - mn0), sc1 = ex2f(m1 - mn1);

        float rs0 = 0.f, rs1 = 0.f;
#pragma unroll
        for (int nf = 0; nf < 8; nf++) {
            sf[nf][0] = ex2f(sf[nf][0] - mn0);
            sf[nf][1] = ex2f(sf[nf][1] - mn0);
            sf[nf][2] = ex2f(sf[nf][2] - mn1);
            sf[nf][3] = ex2f(sf[nf][3] - mn1);
            rs0 += sf[nf][0] + sf[nf][1];
            rs1 += sf[nf][2] + sf[nf][3];
        }
        rs0 += __shfl_xor_sync(0xffffffffu, rs0, 1);
        rs0 += __shfl_xor_sync(0xffffffffu, rs0, 2);
        rs1 += __shfl_xor_sync(0xffffffffu, rs1, 1);
        rs1 += __shfl_xor_sync(0xffffffffu, rs1, 2);

        l0 = l0 * sc0 + rs0;  m0 = mn0;
        l1 = l1 * sc1 + rs1;  m1 = mn1;
#pragma unroll
        for (int nf = 0; nf < 8; nf++) {
            o[nf][0] *= sc0;  o[nf][1] *= sc0;
            o[nf][2] *= sc1;  o[nf][3] *= sc1;
        }

        // P -> warp-private smem
#pragma unroll
        for (int nf = 0; nf < 8; nf++) {
            int c = nf * 8 + 2 * q4;
            float2 p01 = make_float2(__uint_as_float(f2tf32(sf[nf][0])),
                                     __uint_as_float(f2tf32(sf[nf][1])));
            float2 p23 = make_float2(__uint_as_float(f2tf32(sf[nf][2])),
                                     __uint_as_float(f2tf32(sf[nf][3])));
            *(float2*)&Pw[(g    ) * KVPAD + c] = p01;
            *(float2*)&Pw[(g + 8) * KVPAD + c] = p23;
        }
        __syncwarp();

        // O += P @ V
#pragma unroll
        for (int ks = 0; ks < 8; ks++) {
            uint32_t a0 = __float_as_uint(Pw[(g    ) * KVPAD + ks * 8 + q4]);
            uint32_t a1 = __float_as_uint(Pw[(g + 8) * KVPAD + ks * 8 + q4]);
            uint32_t a2 = __float_as_uint(Pw[(g    ) * KVPAD + ks * 8 + q4 + 4]);
            uint32_t a3 = __float_as_uint(Pw[(g + 8) * KVPAD + ks * 8 + q4 + 4]);
#pragma unroll
            for (int nf = 0; nf < 8; nf++) {
                uint32_t b0 = __float_as_uint(Vs[(nf * 8 + g) * KVPAD + ks * 8 + q4]);
                uint32_t b1 = __float_as_uint(Vs[(nf * 8 + g) * KVPAD + ks * 8 + q4 + 4]);
                mma_tf32(o[nf], a0, a1, a2, a3, b0, b1);
            }
        }
        __syncthreads();
    }

    // write partial (unnormalized O, m, l)
    const int slot = b * SLOTS + idx;
    float* po = g_po + (size_t)slot * 4096;
    const int r0 = w * 16 + g;
    const int r1 = r0 + 8;
#pragma unroll
    for (int nf = 0; nf < 8; nf++) {
        int col = nf * 8 + 2 * q4;
        *(float2*)(po + r0 * 64 + col) = make_float2(o[nf][0], o[nf][1]);
        *(float2*)(po + r1 * 64 + col) = make_float2(o[nf][2], o[nf][3]);
    }
    if (q4 == 0) {
        g_pm[slot * 64 + r0] = m0;  g_pm[slot * 64 + r1] = m1;
        g_pl[slot * 64 + r0] = l0;  g_pl[slot * 64 + r1] = l1;
    }
}

// ---------------------------------------------------------------------------
// Merge: combine <=4 partials per query row. 32 threads per row, 8 rows/block.
// ---------------------------------------------------------------------------
__global__ __launch_bounds__(256) void merge_kernel(float* __restrict__ out)
{
    const int gid  = blockIdx.x * 8 + (threadIdx.x >> 5);   // row 0..16383
    const int lane = threadIdx.x & 31;
    const int b = gid >> 11;
    const int q = gid & 2047;
    const int qt    = q >> 6;
    const int rowin = q & 63;
    const int grp   = qt >> 3;
    const int nch   = grp + 1;
    const int base  = b * SLOTS + 4 * grp * (grp + 1) + (qt - 8 * grp) * (grp + 1);

    float mv[4];
    float M = -1e30f;
    for (int c = 0; c < nch; c++) {
        mv[c] = g_pm[(base + c) * 64 + rowin];
        M = fmaxf(M, mv[c]);
    }
    float L = 0.f, o0 = 0.f, o1 = 0.f;
    const int col = lane * 2;
    for (int c = 0; c < nch; c++) {
        float wgt = ex2f(mv[c] - M);
        L += wgt * g_pl[(base + c) * 64 + rowin];
        float2 ov = *(const float2*)(g_po + ((size_t)(base + c) * 64 + rowin) * 64 + col);
        o0 += wgt * ov.x;
        o1 += wgt * ov.y;
    }
    float inv = 1.f / L;
    *(float2*)(out + ((size_t)b * Tc + q) * Hc + col) = make_float2(o0 * inv, o1 * inv);
}

// ---------------------------------------------------------------------------
extern "C" void kernel_launch(void* const* d_in, const int* in_sizes, int n_in,
                              void* d_out, int out_size)
{
    (void)in_sizes; (void)n_in; (void)out_size;
    const float* x  = (const float*)d_in[0];
    const float* Wk = (const float*)d_in[1];
    const float* bk = (const float*)d_in[2];
    const float* Wq = (const float*)d_in[3];
    const float* bq = (const float*)d_in[4];
    const float* Wv = (const float*)d_in[5];
    const float* bv = (const float*)d_in[6];
    float* out = (float*)d_out;

    cudaFuncSetAttribute(proj_kernel, cudaFuncAttributeMaxDynamicSharedMemorySize, PSMEM);
    cudaFuncSetAttribute(attn_partial_kernel, cudaFuncAttributeMaxDynamicSharedMemorySize, ASMEM);

    proj_kernel<<<(Bc * Tc) / 64, 384, PSMEM>>>(x, Wq, Wk, Wv, bq, bk, bv);

    dim3 ag(SLOTS, Bc);
    attn_partial_kernel<<<ag, 128, ASMEM>>>();

    merge_kernel<<<(Bc * Tc) / 8, 256>>>(out);
}

// round 8
// speedup vs baseline: 3.2758x; 1.3443x over previous
#include <cuda_runtime.h>
#include <cuda_bf16.h>
#include <cstdint>

constexpr int Bc = 8;
constexpr int Tc = 2048;
constexpr int Dc = 1024;
constexpr int Hc = 64;

// q/k/v projections
__device__ float g_q[Bc * Tc * Hc];
__device__ float g_k[Bc * Tc * Hc];
__device__ float g_v[Bc * Tc * Hc];

// split-KV partials: 80 chunk-slots per batch (qtile i has ceil((i+1)/8) chunks)
constexpr int SLOTS = 80;
__device__ float g_po[Bc * SLOTS * 64 * 64];   // unnormalized O
__device__ float g_pm[Bc * SLOTS * 64];        // row max (exp2 space)
__device__ float g_pl[Bc * SLOTS * 64];        // row sum

__device__ __forceinline__ uint32_t f2tf32(float x) {
    uint32_t u;
    asm("cvt.rna.tf32.f32 %0, %1;" : "=r"(u) : "f"(x));
    return u;
}
__device__ __forceinline__ float ex2f(float x) {
    float y;
    asm("ex2.approx.ftz.f32 %0, %1;" : "=f"(y) : "f"(x));
    return y;
}
__device__ __forceinline__ void mma_tf32(float* c,
    uint32_t a0, uint32_t a1, uint32_t a2, uint32_t a3,
    uint32_t b0, uint32_t b1)
{
    asm volatile(
        "mma.sync.aligned.m16n8k8.row.col.f32.tf32.tf32.f32 "
        "{%0,%1,%2,%3}, {%4,%5,%6,%7}, {%8,%9}, {%0,%1,%2,%3};"
        : "+f"(c[0]), "+f"(c[1]), "+f"(c[2]), "+f"(c[3])
        : "r"(a0), "r"(a1), "r"(a2), "r"(a3), "r"(b0), "r"(b1));
}
__device__ __forceinline__ uint32_t smem_u32(const void* p) {
    return (uint32_t)__cvta_generic_to_shared(p);
}
__device__ __forceinline__ void cpa16(uint32_t dst, const void* src) {
    asm volatile("cp.async.ca.shared.global [%0], [%1], 16;" :: "r"(dst), "l"(src));
}
#define CP_COMMIT() asm volatile("cp.async.commit_group;")

// ---------------------------------------------------------------------------
// Fused projection, cp.async 3-stage pipeline, tf32 cvt at fragment load.
// 384 threads = 12 warps; warp w: projection p = w>>2, row sub-tile ww = w&3.
// Warp tile: m32 x n64. BM=128, BK=32, 32 K-iterations.
// Xs [128][36] (banks 4g+q4: conflict-free), Ws [3][32][72] (banks
// 8((q4+nf)%4)+g: conflict-free).
// ---------------------------------------------------------------------------
#define XPAD   36
#define WPAD   72
#define XS_F   (128 * XPAD)               // 4608 floats
#define STAGEF (XS_F + 3 * 32 * WPAD)     // 11520 floats per stage
#define PSTAGES 3
#define PSMEM  (PSTAGES * STAGEF * 4)     // 138240 bytes

__device__ __forceinline__ void proj_stage_async(
    uint32_t sb, const float* __restrict__ x,
    const float* const* Wp, int m0, int k0, int t)
{
    // x tile [128][32]: 1024 16B chunks
    for (int idx = t; idx < 1024; idx += 384) {
        int row = idx >> 3;
        int c4  = (idx & 7) << 2;
        cpa16(sb + (uint32_t)(row * XPAD + c4) * 4,
              x + (size_t)(m0 + row) * Dc + k0 + c4);
    }
    // W tiles 3x[32][64]: 1536 16B chunks, 4 per thread
#pragma unroll
    for (int i = 0; i < 4; i++) {
        int idx = t + i * 384;
        int p   = idx >> 9;
        int rem = idx & 511;
        int row = rem >> 4;
        int c4  = (rem & 15) << 2;
        cpa16(sb + (uint32_t)(XS_F + (p * 32 + row) * WPAD + c4) * 4,
              Wp[p] + (size_t)(k0 + row) * Hc + c4);
    }
}

__global__ __launch_bounds__(384, 1) void proj_kernel(
    const float* __restrict__ x,
    const float* __restrict__ Wq, const float* __restrict__ Wk, const float* __restrict__ Wv,
    const float* __restrict__ bq, const float* __restrict__ bk, const float* __restrict__ bv)
{
    extern __shared__ float psm[];
    const float* Wp[3] = { Wq, Wk, Wv };

    const int t    = threadIdx.x;
    const int w    = t >> 5;
    const int p    = w >> 2;      // projection
    const int ww   = w & 3;       // m32 row sub-tile
    const int lane = t & 31;
    const int g    = lane >> 2;
    const int q4   = lane & 3;
    const int m0   = blockIdx.x * 128;

    const uint32_t sb = smem_u32(psm);

    float acc[2][8][4];
#pragma unroll
    for (int i = 0; i < 2; i++)
#pragma unroll
        for (int nf = 0; nf < 8; nf++)
#pragma unroll
            for (int j = 0; j < 4; j++) acc[i][nf][j] = 0.f;

    // prologue: stages 0,1
    proj_stage_async(sb,                        x, Wp, m0, 0,  t);
    CP_COMMIT();
    proj_stage_async(sb + STAGEF * 4,           x, Wp, m0, 32, t);
    CP_COMMIT();

    for (int it = 0; it < 32; it++) {
        // issue stage it+2 (overwrites buffer consumed at it-1), then wait for it
        if (it < 30) {
            proj_stage_async(sb + (uint32_t)((it + 2) % 3) * STAGEF * 4,
                             x, Wp, m0, (it + 2) * 32, t);
            CP_COMMIT();
            asm volatile("cp.async.wait_group 2;");
        } else if (it == 30) {
            asm volatile("cp.async.wait_group 1;");
        } else {
            asm volatile("cp.async.wait_group 0;");
        }
        __syncthreads();

        const float* Xs = psm + (it % 3) * STAGEF;
        const float* Ws = Xs + XS_F + p * 32 * WPAD;

#pragma unroll
        for (int ks = 0; ks < 4; ks++) {
            const int kc = ks * 8 + q4;
            uint32_t a[2][4];
#pragma unroll
            for (int i = 0; i < 2; i++) {
                const int r = ww * 32 + i * 16 + g;
                a[i][0] = f2tf32(Xs[(r    ) * XPAD + kc]);
                a[i][1] = f2tf32(Xs[(r + 8) * XPAD + kc]);
                a[i][2] = f2tf32(Xs[(r    ) * XPAD + kc + 4]);
                a[i][3] = f2tf32(Xs[(r + 8) * XPAD + kc + 4]);
            }
#pragma unroll
            for (int nf = 0; nf < 8; nf++) {
                uint32_t b0 = f2tf32(Ws[(kc    ) * WPAD + nf * 8 + g]);
                uint32_t b1 = f2tf32(Ws[(kc + 4) * WPAD + nf * 8 + g]);
                mma_tf32(acc[0][nf], a[0][0], a[0][1], a[0][2], a[0][3], b0, b1);
                mma_tf32(acc[1][nf], a[1][0], a[1][1], a[1][2], a[1][3], b0, b1);
            }
        }
        __syncthreads();   // all warps done with buffer (it%3) before restage
    }

    const float* biases[3] = { bq, bk, bv };
    float* outs[3] = { g_q, g_k, g_v };
    float* out = outs[p];
    const float* bias = biases[p];
#pragma unroll
    for (int i = 0; i < 2; i++) {
        const int r0 = m0 + ww * 32 + i * 16 + g;
#pragma unroll
        for (int nf = 0; nf < 8; nf++) {
            int col = nf * 8 + 2 * q4;
            float b0 = bias[col], b1 = bias[col + 1];
            float2 v0 = make_float2(acc[i][nf][0] + b0, acc[i][nf][1] + b1);
            float2 v1 = make_float2(acc[i][nf][2] + b0, acc[i][nf][3] + b1);
            *(float2*)(out + (size_t)r0 * Hc + col)       = v0;
            *(float2*)(out + (size_t)(r0 + 8) * Hc + col) = v1;
        }
    }
}

// ---------------------------------------------------------------------------
// Attention partials: block = (batch, chunk-slot). 64 queries, 4 warps,
// processes <=8 KV tiles (64-wide), ping-pong staged. Writes (O, m, l).
// ---------------------------------------------------------------------------
#define KVPAD 68
#define TILEF (64 * KVPAD)
#define ASMEM ((4 * TILEF + 4 * 16 * KVPAD) * 4)   // 87040 bytes

__device__ __forceinline__ void attn_stage(
    float* Kbuf, float* Vbuf,
    const float* __restrict__ kb, const float* __restrict__ vb,
    int kn0, int t)
{
    const int row  = t & 63;
    const int half = (t >> 6) * 32;
    {
        const float4* src = (const float4*)(kb + (size_t)(kn0 + row) * Hc + half);
        float* d = &Kbuf[row * KVPAD + half];
#pragma unroll
        for (int i = 0; i < 8; i++) {
            float4 v = src[i];
            d[i * 4 + 0] = __uint_as_float(f2tf32(v.x));
            d[i * 4 + 1] = __uint_as_float(f2tf32(v.y));
            d[i * 4 + 2] = __uint_as_float(f2tf32(v.z));
            d[i * 4 + 3] = __uint_as_float(f2tf32(v.w));
        }
    }
    {
        const float4* src = (const float4*)(vb + (size_t)(kn0 + row) * Hc + half);
#pragma unroll
        for (int i = 0; i < 8; i++) {
            float4 v = src[i];
            int h = half + i * 4;
            Vbuf[(h + 0) * KVPAD + row] = __uint_as_float(f2tf32(v.x));
            Vbuf[(h + 1) * KVPAD + row] = __uint_as_float(f2tf32(v.y));
            Vbuf[(h + 2) * KVPAD + row] = __uint_as_float(f2tf32(v.z));
            Vbuf[(h + 3) * KVPAD + row] = __uint_as_float(f2tf32(v.w));
        }
    }
}

__global__ __launch_bounds__(128) void attn_partial_kernel()
{
    extern __shared__ float sm[];
    float* Kb[2] = { sm, sm + TILEF };
    float* Vb[2] = { sm + 2 * TILEF, sm + 3 * TILEF };
    float* Psw   = sm + 4 * TILEF;

    const int b   = blockIdx.y;
    const int idx = (int)(gridDim.x - 1 - blockIdx.x);   // heavy chunks first

    int qt = 0, ch = 0;
#pragma unroll
    for (int gg = 3; gg >= 0; gg--) {
        int s = 4 * gg * (gg + 1);
        if (idx >= s) { qt = 8 * gg + (idx - s) / (gg + 1); ch = (idx - s) % (gg + 1); break; }
    }
    const int q0  = qt * 64;
    const int kt0 = ch * 8;
    const int kt1 = min(kt0 + 8, qt + 1);

    const int t    = threadIdx.x;
    const int w    = t >> 5;
    const int lane = t & 31;
    const int g    = lane >> 2;
    const int q4   = lane & 3;
    float* Pw = Psw + w * 16 * KVPAD;

    const float* qb = g_q + (size_t)b * Tc * Hc;
    const float* kb = g_k + (size_t)b * Tc * Hc;
    const float* vb = g_v + (size_t)b * Tc * Hc;

    const float SC = 0.125f * 1.44269504f;
    uint32_t qa[8][4];
    {
        const float* r0 = qb + (size_t)(q0 + w * 16 + g) * Hc;
        const float* r1 = r0 + 8 * Hc;
#pragma unroll
        for (int ks = 0; ks < 8; ks++) {
            qa[ks][0] = f2tf32(r0[ks * 8 + q4] * SC);
            qa[ks][1] = f2tf32(r1[ks * 8 + q4] * SC);
            qa[ks][2] = f2tf32(r0[ks * 8 + q4 + 4] * SC);
            qa[ks][3] = f2tf32(r1[ks * 8 + q4 + 4] * SC);
        }
    }

    float o[8][4];
#pragma unroll
    for (int nf = 0; nf < 8; nf++)
#pragma unroll
        for (int j = 0; j < 4; j++) o[nf][j] = 0.f;
    float m0 = -1e30f, m1 = -1e30f, l0 = 0.f, l1 = 0.f;

    attn_stage(Kb[0], Vb[0], kb, vb, kt0 * 64, t);
    __syncthreads();

    for (int kt = kt0; kt < kt1; kt++) {
        const int buf = (kt - kt0) & 1;
        if (kt + 1 < kt1)
            attn_stage(Kb[buf ^ 1], Vb[buf ^ 1], kb, vb, (kt + 1) * 64, t);

        const float* Ks = Kb[buf];
        const float* Vs = Vb[buf];
        const int kn0 = kt * 64;

        float sf[8][4];
#pragma unroll
        for (int nf = 0; nf < 8; nf++) {
            sf[nf][0] = sf[nf][1] = sf[nf][2] = sf[nf][3] = 0.f;
#pragma unroll
            for (int ks = 0; ks < 8; ks++) {
                uint32_t b0 = __float_as_uint(Ks[(nf * 8 + g) * KVPAD + ks * 8 + q4]);
                uint32_t b1 = __float_as_uint(Ks[(nf * 8 + g) * KVPAD + ks * 8 + q4 + 4]);
                mma_tf32(sf[nf], qa[ks][0], qa[ks][1], qa[ks][2], qa[ks][3], b0, b1);
            }
        }

        if (kt == qt) {
            const int r0 = q0 + w * 16 + g;
            const int r1 = r0 + 8;
#pragma unroll
            for (int nf = 0; nf < 8; nf++) {
                int c0 = kn0 + nf * 8 + 2 * q4;
                if (c0     > r0) sf[nf][0] = -1e30f;
                if (c0 + 1 > r0) sf[nf][1] = -1e30f;
                if (c0     > r1) sf[nf][2] = -1e30f;
                if (c0 + 1 > r1) sf[nf][3] = -1e30f;
            }
        }

        float mx0 = -1e30f, mx1 = -1e30f;
#pragma unroll
        for (int nf = 0; nf < 8; nf++) {
            mx0 = fmaxf(mx0, fmaxf(sf[nf][0], sf[nf][1]));
            mx1 = fmaxf(mx1, fmaxf(sf[nf][2], sf[nf][3]));
        }
        mx0 = fmaxf(mx0, __shfl_xor_sync(0xffffffffu, mx0, 1));
        mx0 = fmaxf(mx0, __shfl_xor_sync(0xffffffffu, mx0, 2));
        mx1 = fmaxf(mx1, __shfl_xor_sync(0xffffffffu, mx1, 1));
        mx1 = fmaxf(mx1, __shfl_xor_sync(0xffffffffu, mx1, 2));

        float mn0 = fmaxf(m0, mx0), mn1 = fmaxf(m1, mx1);
        float sc0 = ex2f(m0 - mn0), sc1 = ex2f(m1 - mn1);

        float rs0 = 0.f, rs1 = 0.f;
#pragma unroll
        for (int nf = 0; nf < 8; nf++) {
            sf[nf][0] = ex2f(sf[nf][0] - mn0);
            sf[nf][1] = ex2f(sf[nf][1] - mn0);
            sf[nf][2] = ex2f(sf[nf][2] - mn1);
            sf[nf][3] = ex2f(sf[nf][3] - mn1);
            rs0 += sf[nf][0] + sf[nf][1];
            rs1 += sf[nf][2] + sf[nf][3];
        }
        rs0 += __shfl_xor_sync(0xffffffffu, rs0, 1);
        rs0 += __shfl_xor_sync(0xffffffffu, rs0, 2);
        rs1 += __shfl_xor_sync(0xffffffffu, rs1, 1);
        rs1 += __shfl_xor_sync(0xffffffffu, rs1, 2);

        l0 = l0 * sc0 + rs0;  m0 = mn0;
        l1 = l1 * sc1 + rs1;  m1 = mn1;
#pragma unroll
        for (int nf = 0; nf < 8; nf++) {
            o[nf][0] *= sc0;  o[nf][1] *= sc0;
            o[nf][2] *= sc1;  o[nf][3] *= sc1;
        }

#pragma unroll
        for (int nf = 0; nf < 8; nf++) {
            int c = nf * 8 + 2 * q4;
            float2 p01 = make_float2(__uint_as_float(f2tf32(sf[nf][0])),
                                     __uint_as_float(f2tf32(sf[nf][1])));
            float2 p23 = make_float2(__uint_as_float(f2tf32(sf[nf][2])),
                                     __uint_as_float(f2tf32(sf[nf][3])));
            *(float2*)&Pw[(g    ) * KVPAD + c] = p01;
            *(float2*)&Pw[(g + 8) * KVPAD + c] = p23;
        }
        __syncwarp();

#pragma unroll
        for (int ks = 0; ks < 8; ks++) {
            uint32_t a0 = __float_as_uint(Pw[(g    ) * KVPAD + ks * 8 + q4]);
            uint32_t a1 = __float_as_uint(Pw[(g + 8) * KVPAD + ks * 8 + q4]);
            uint32_t a2 = __float_as_uint(Pw[(g    ) * KVPAD + ks * 8 + q4 + 4]);
            uint32_t a3 = __float_as_uint(Pw[(g + 8) * KVPAD + ks * 8 + q4 + 4]);
#pragma unroll
            for (int nf = 0; nf < 8; nf++) {
                uint32_t b0 = __float_as_uint(Vs[(nf * 8 + g) * KVPAD + ks * 8 + q4]);
                uint32_t b1 = __float_as_uint(Vs[(nf * 8 + g) * KVPAD + ks * 8 + q4 + 4]);
                mma_tf32(o[nf], a0, a1, a2, a3, b0, b1);
            }
        }
        __syncthreads();
    }

    const int slot = b * SLOTS + idx;
    float* po = g_po + (size_t)slot * 4096;
    const int r0 = w * 16 + g;
    const int r1 = r0 + 8;
#pragma unroll
    for (int nf = 0; nf < 8; nf++) {
        int col = nf * 8 + 2 * q4;
        *(float2*)(po + r0 * 64 + col) = make_float2(o[nf][0], o[nf][1]);
        *(float2*)(po + r1 * 64 + col) = make_float2(o[nf][2], o[nf][3]);
    }
    if (q4 == 0) {
        g_pm[slot * 64 + r0] = m0;  g_pm[slot * 64 + r1] = m1;
        g_pl[slot * 64 + r0] = l0;  g_pl[slot * 64 + r1] = l1;
    }
}

// ---------------------------------------------------------------------------
// Merge: combine <=4 partials per query row. 32 threads per row, 8 rows/block.
// ---------------------------------------------------------------------------
__global__ __launch_bounds__(256) void merge_kernel(float* __restrict__ out)
{
    const int gid  = blockIdx.x * 8 + (threadIdx.x >> 5);
    const int lane = threadIdx.x & 31;
    const int b = gid >> 11;
    const int q = gid & 2047;
    const int qt    = q >> 6;
    const int rowin = q & 63;
    const int grp   = qt >> 3;
    const int nch   = grp + 1;
    const int base  = b * SLOTS + 4 * grp * (grp + 1) + (qt - 8 * grp) * (grp + 1);

    float mv[4];
    float M = -1e30f;
    for (int c = 0; c < nch; c++) {
        mv[c] = g_pm[(base + c) * 64 + rowin];
        M = fmaxf(M, mv[c]);
    }
    float L = 0.f, o0 = 0.f, o1 = 0.f;
    const int col = lane * 2;
    for (int c = 0; c < nch; c++) {
        float wgt = ex2f(mv[c] - M);
        L += wgt * g_pl[(base + c) * 64 + rowin];
        float2 ov = *(const float2*)(g_po + ((size_t)(base + c) * 64 + rowin) * 64 + col);
        o0 += wgt * ov.x;
        o1 += wgt * ov.y;
    }
    float inv = 1.f / L;
    *(float2*)(out + ((size_t)b * Tc + q) * Hc + col) = make_float2(o0 * inv, o1 * inv);
}

// ---------------------------------------------------------------------------
extern "C" void kernel_launch(void* const* d_in, const int* in_sizes, int n_in,
                              void* d_out, int out_size)
{
    (void)in_sizes; (void)n_in; (void)out_size;
    const float* x  = (const float*)d_in[0];
    const float* Wk = (const float*)d_in[1];
    const float* bk = (const float*)d_in[2];
    const float* Wq = (const float*)d_in[3];
    const float* bq = (const float*)d_in[4];
    const float* Wv = (const float*)d_in[5];
    const float* bv = (const float*)d_in[6];
    float* out = (float*)d_out;

    cudaFuncSetAttribute(proj_kernel, cudaFuncAttributeMaxDynamicSharedMemorySize, PSMEM);
    cudaFuncSetAttribute(attn_partial_kernel, cudaFuncAttributeMaxDynamicSharedMemorySize, ASMEM);

    proj_kernel<<<(Bc * Tc) / 128, 384, PSMEM>>>(x, Wq, Wk, Wv, bq, bk, bv);

    dim3 ag(SLOTS, Bc);
    attn_partial_kernel<<<ag, 128, ASMEM>>>();

    merge_kernel<<<(Bc * Tc) / 8, 256>>>(out);
}

// round 9
// speedup vs baseline: 3.2821x; 1.0019x over previous
#include <cuda_runtime.h>
#include <cuda_bf16.h>
#include <cstdint>

constexpr int Bc = 8;
constexpr int Tc = 2048;
constexpr int Dc = 1024;
constexpr int Hc = 64;

// q/k/v projections
__device__ float g_q[Bc * Tc * Hc];
__device__ float g_k[Bc * Tc * Hc];
__device__ float g_v[Bc * Tc * Hc];

// split-KV partials: 80 chunk-slots per batch (qtile i has ceil((i+1)/8) chunks)
constexpr int SLOTS = 80;
__device__ float g_po[Bc * SLOTS * 64 * 64];   // unnormalized O
__device__ float g_pm[Bc * SLOTS * 64];        // row max (exp2 space)
__device__ float g_pl[Bc * SLOTS * 64];        // row sum

__device__ __forceinline__ uint32_t f2tf32(float x) {
    uint32_t u;
    asm("cvt.rna.tf32.f32 %0, %1;" : "=r"(u) : "f"(x));
    return u;
}
__device__ __forceinline__ float ex2f(float x) {
    float y;
    asm("ex2.approx.ftz.f32 %0, %1;" : "=f"(y) : "f"(x));
    return y;
}
__device__ __forceinline__ void mma_tf32(float* c,
    uint32_t a0, uint32_t a1, uint32_t a2, uint32_t a3,
    uint32_t b0, uint32_t b1)
{
    asm volatile(
        "mma.sync.aligned.m16n8k8.row.col.f32.tf32.tf32.f32 "
        "{%0,%1,%2,%3}, {%4,%5,%6,%7}, {%8,%9}, {%0,%1,%2,%3};"
        : "+f"(c[0]), "+f"(c[1]), "+f"(c[2]), "+f"(c[3])
        : "r"(a0), "r"(a1), "r"(a2), "r"(a3), "r"(b0), "r"(b1));
}
__device__ __forceinline__ uint32_t smem_u32(const void* p) {
    return (uint32_t)__cvta_generic_to_shared(p);
}
__device__ __forceinline__ void cpa16(uint32_t dst, const void* src) {
    asm volatile("cp.async.ca.shared.global [%0], [%1], 16;" :: "r"(dst), "l"(src));
}
#define CP_COMMIT() asm volatile("cp.async.commit_group;")

// ---------------------------------------------------------------------------
// Fused projection, cp.async 3-stage pipeline, tf32 cvt at fragment load.
// 384 threads = 12 warps; warp w: projection p = w>>2, row sub-tile ww = w&3.
// Warp tile: m32 x n64. BM=128, BK=32, 32 K-iterations.
// Xs [128][36] (banks 4g+q4: conflict-free), Ws [3][32][72] (banks
// 8((q4+nf)%4)+g: conflict-free).
// ---------------------------------------------------------------------------
#define XPAD   36
#define WPAD   72
#define XS_F   (128 * XPAD)               // 4608 floats
#define STAGEF (XS_F + 3 * 32 * WPAD)     // 11520 floats per stage
#define PSTAGES 3
#define PSMEM  (PSTAGES * STAGEF * 4)     // 138240 bytes

__device__ __forceinline__ void proj_stage_async(
    uint32_t sb, const float* __restrict__ x,
    const float* const* Wp, int m0, int k0, int t)
{
    // x tile [128][32]: 1024 16B chunks
    for (int idx = t; idx < 1024; idx += 384) {
        int row = idx >> 3;
        int c4  = (idx & 7) << 2;
        cpa16(sb + (uint32_t)(row * XPAD + c4) * 4,
              x + (size_t)(m0 + row) * Dc + k0 + c4);
    }
    // W tiles 3x[32][64]: 1536 16B chunks, 4 per thread
#pragma unroll
    for (int i = 0; i < 4; i++) {
        int idx = t + i * 384;
        int p   = idx >> 9;
        int rem = idx & 511;
        int row = rem >> 4;
        int c4  = (rem & 15) << 2;
        cpa16(sb + (uint32_t)(XS_F + (p * 32 + row) * WPAD + c4) * 4,
              Wp[p] + (size_t)(k0 + row) * Hc + c4);
    }
}

__global__ __launch_bounds__(384, 1) void proj_kernel(
    const float* __restrict__ x,
    const float* __restrict__ Wq, const float* __restrict__ Wk, const float* __restrict__ Wv,
    const float* __restrict__ bq, const float* __restrict__ bk, const float* __restrict__ bv)
{
    extern __shared__ float psm[];
    const float* Wp[3] = { Wq, Wk, Wv };

    const int t    = threadIdx.x;
    const int w    = t >> 5;
    const int p    = w >> 2;      // projection
    const int ww   = w & 3;       // m32 row sub-tile
    const int lane = t & 31;
    const int g    = lane >> 2;
    const int q4   = lane & 3;
    const int m0   = blockIdx.x * 128;

    const uint32_t sb = smem_u32(psm);

    float acc[2][8][4];
#pragma unroll
    for (int i = 0; i < 2; i++)
#pragma unroll
        for (int nf = 0; nf < 8; nf++)
#pragma unroll
            for (int j = 0; j < 4; j++) acc[i][nf][j] = 0.f;

    // prologue: stages 0,1
    proj_stage_async(sb,                        x, Wp, m0, 0,  t);
    CP_COMMIT();
    proj_stage_async(sb + STAGEF * 4,           x, Wp, m0, 32, t);
    CP_COMMIT();

    for (int it = 0; it < 32; it++) {
        // issue stage it+2 (overwrites buffer consumed at it-1), then wait for it
        if (it < 30) {
            proj_stage_async(sb + (uint32_t)((it + 2) % 3) * STAGEF * 4,
                             x, Wp, m0, (it + 2) * 32, t);
            CP_COMMIT();
            asm volatile("cp.async.wait_group 2;");
        } else if (it == 30) {
            asm volatile("cp.async.wait_group 1;");
        } else {
            asm volatile("cp.async.wait_group 0;");
        }
        __syncthreads();

        const float* Xs = psm + (it % 3) * STAGEF;
        const float* Ws = Xs + XS_F + p * 32 * WPAD;

#pragma unroll
        for (int ks = 0; ks < 4; ks++) {
            const int kc = ks * 8 + q4;
            uint32_t a[2][4];
#pragma unroll
            for (int i = 0; i < 2; i++) {
                const int r = ww * 32 + i * 16 + g;
                a[i][0] = f2tf32(Xs[(r    ) * XPAD + kc]);
                a[i][1] = f2tf32(Xs[(r + 8) * XPAD + kc]);
                a[i][2] = f2tf32(Xs[(r    ) * XPAD + kc + 4]);
                a[i][3] = f2tf32(Xs[(r + 8) * XPAD + kc + 4]);
            }
#pragma unroll
            for (int nf = 0; nf < 8; nf++) {
                uint32_t b0 = f2tf32(Ws[(kc    ) * WPAD + nf * 8 + g]);
                uint32_t b1 = f2tf32(Ws[(kc + 4) * WPAD + nf * 8 + g]);
                mma_tf32(acc[0][nf], a[0][0], a[0][1], a[0][2], a[0][3], b0, b1);
                mma_tf32(acc[1][nf], a[1][0], a[1][1], a[1][2], a[1][3], b0, b1);
            }
        }
        __syncthreads();   // all warps done with buffer (it%3) before restage
    }

    const float* biases[3] = { bq, bk, bv };
    float* outs[3] = { g_q, g_k, g_v };
    float* out = outs[p];
    const float* bias = biases[p];
#pragma unroll
    for (int i = 0; i < 2; i++) {
        const int r0 = m0 + ww * 32 + i * 16 + g;
#pragma unroll
        for (int nf = 0; nf < 8; nf++) {
            int col = nf * 8 + 2 * q4;
            float b0 = bias[col], b1 = bias[col + 1];
            float2 v0 = make_float2(acc[i][nf][0] + b0, acc[i][nf][1] + b1);
            float2 v1 = make_float2(acc[i][nf][2] + b0, acc[i][nf][3] + b1);
            *(float2*)(out + (size_t)r0 * Hc + col)       = v0;
            *(float2*)(out + (size_t)(r0 + 8) * Hc + col) = v1;
        }
    }
}

// ---------------------------------------------------------------------------
// Attention partials: block = (batch, chunk-slot). 64 queries, 4 warps,
// processes <=8 KV tiles (64-wide), ping-pong staged. Writes (O, m, l).
// ---------------------------------------------------------------------------
#define KVPAD 68
#define TILEF (64 * KVPAD)
#define ASMEM ((4 * TILEF + 4 * 16 * KVPAD) * 4)   // 87040 bytes

__device__ __forceinline__ void attn_stage(
    float* Kbuf, float* Vbuf,
    const float* __restrict__ kb, const float* __restrict__ vb,
    int kn0, int t)
{
    const int row  = t & 63;
    const int half = (t >> 6) * 32;
    {
        const float4* src = (const float4*)(kb + (size_t)(kn0 + row) * Hc + half);
        float* d = &Kbuf[row * KVPAD + half];
#pragma unroll
        for (int i = 0; i < 8; i++) {
            float4 v = src[i];
            d[i * 4 + 0] = __uint_as_float(f2tf32(v.x));
            d[i * 4 + 1] = __uint_as_float(f2tf32(v.y));
            d[i * 4 + 2] = __uint_as_float(f2tf32(v.z));
            d[i * 4 + 3] = __uint_as_float(f2tf32(v.w));
        }
    }
    {
        const float4* src = (const float4*)(vb + (size_t)(kn0 + row) * Hc + half);
#pragma unroll
        for (int i = 0; i < 8; i++) {
            float4 v = src[i];
            int h = half + i * 4;
            Vbuf[(h + 0) * KVPAD + row] = __uint_as_float(f2tf32(v.x));
            Vbuf[(h + 1) * KVPAD + row] = __uint_as_float(f2tf32(v.y));
            Vbuf[(h + 2) * KVPAD + row] = __uint_as_float(f2tf32(v.z));
            Vbuf[(h + 3) * KVPAD + row] = __uint_as_float(f2tf32(v.w));
        }
    }
}

__global__ __launch_bounds__(128) void attn_partial_kernel()
{
    extern __shared__ float sm[];
    float* Kb[2] = { sm, sm + TILEF };
    float* Vb[2] = { sm + 2 * TILEF, sm + 3 * TILEF };
    float* Psw   = sm + 4 * TILEF;

    const int b   = blockIdx.y;
    const int idx = (int)(gridDim.x - 1 - blockIdx.x);   // heavy chunks first

    int qt = 0, ch = 0;
#pragma unroll
    for (int gg = 3; gg >= 0; gg--) {
        int s = 4 * gg * (gg + 1);
        if (idx >= s) { qt = 8 * gg + (idx - s) / (gg + 1); ch = (idx - s) % (gg + 1); break; }
    }
    const int q0  = qt * 64;
    const int kt0 = ch * 8;
    const int kt1 = min(kt0 + 8, qt + 1);

    const int t    = threadIdx.x;
    const int w    = t >> 5;
    const int lane = t & 31;
    const int g    = lane >> 2;
    const int q4   = lane & 3;
    float* Pw = Psw + w * 16 * KVPAD;

    const float* qb = g_q + (size_t)b * Tc * Hc;
    const float* kb = g_k + (size_t)b * Tc * Hc;
    const float* vb = g_v + (size_t)b * Tc * Hc;

    const float SC = 0.125f * 1.44269504f;
    uint32_t qa[8][4];
    {
        const float* r0 = qb + (size_t)(q0 + w * 16 + g) * Hc;
        const float* r1 = r0 + 8 * Hc;
#pragma unroll
        for (int ks = 0; ks < 8; ks++) {
            qa[ks][0] = f2tf32(r0[ks * 8 + q4] * SC);
            qa[ks][1] = f2tf32(r1[ks * 8 + q4] * SC);
            qa[ks][2] = f2tf32(r0[ks * 8 + q4 + 4] * SC);
            qa[ks][3] = f2tf32(r1[ks * 8 + q4 + 4] * SC);
        }
    }

    float o[8][4];
#pragma unroll
    for (int nf = 0; nf < 8; nf++)
#pragma unroll
        for (int j = 0; j < 4; j++) o[nf][j] = 0.f;
    float m0 = -1e30f, m1 = -1e30f, l0 = 0.f, l1 = 0.f;

    attn_stage(Kb[0], Vb[0], kb, vb, kt0 * 64, t);
    __syncthreads();

    for (int kt = kt0; kt < kt1; kt++) {
        const int buf = (kt - kt0) & 1;
        if (kt + 1 < kt1)
            attn_stage(Kb[buf ^ 1], Vb[buf ^ 1], kb, vb, (kt + 1) * 64, t);

        const float* Ks = Kb[buf];
        const float* Vs = Vb[buf];
        const int kn0 = kt * 64;

        float sf[8][4];
#pragma unroll
        for (int nf = 0; nf < 8; nf++) {
            sf[nf][0] = sf[nf][1] = sf[nf][2] = sf[nf][3] = 0.f;
#pragma unroll
            for (int ks = 0; ks < 8; ks++) {
                uint32_t b0 = __float_as_uint(Ks[(nf * 8 + g) * KVPAD + ks * 8 + q4]);
                uint32_t b1 = __float_as_uint(Ks[(nf * 8 + g) * KVPAD + ks * 8 + q4 + 4]);
                mma_tf32(sf[nf], qa[ks][0], qa[ks][1], qa[ks][2], qa[ks][3], b0, b1);
            }
        }

        if (kt == qt) {
            const int r0 = q0 + w * 16 + g;
            const int r1 = r0 + 8;
#pragma unroll
            for (int nf = 0; nf < 8; nf++) {
                int c0 = kn0 + nf * 8 + 2 * q4;
                if (c0     > r0) sf[nf][0] = -1e30f;
                if (c0 + 1 > r0) sf[nf][1] = -1e30f;
                if (c0     > r1) sf[nf][2] = -1e30f;
                if (c0 + 1 > r1) sf[nf][3] = -1e30f;
            }
        }

        float mx0 = -1e30f, mx1 = -1e30f;
#pragma unroll
        for (int nf = 0; nf < 8; nf++) {
            mx0 = fmaxf(mx0, fmaxf(sf[nf][0], sf[nf][1]));
            mx1 = fmaxf(mx1, fmaxf(sf[nf][2], sf[nf][3]));
        }
        mx0 = fmaxf(mx0, __shfl_xor_sync(0xffffffffu, mx0, 1));
        mx0 = fmaxf(mx0, __shfl_xor_sync(0xffffffffu, mx0, 2));
        mx1 = fmaxf(mx1, __shfl_xor_sync(0xffffffffu, mx1, 1));
        mx1 = fmaxf(mx1, __shfl_xor_sync(0xffffffffu, mx1, 2));

        float mn0 = fmaxf(m0, mx0), mn1 = fmaxf(m1, mx1);
        float sc0 = ex2f(m0 - mn0), sc1 = ex2f(m1 - mn1);

        float rs0 = 0.f, rs1 = 0.f;
#pragma unroll
        for (int nf = 0; nf < 8; nf++) {
            sf[nf][0] = ex2f(sf[nf][0] - mn0);
            sf[nf][1] = ex2f(sf[nf][1] - mn0);
            sf[nf][2] = ex2f(sf[nf][2] - mn1);
            sf[nf][3] = ex2f(sf[nf][3] - mn1);
            rs0 += sf[nf][0] + sf[nf][1];
            rs1 += sf[nf][2] + sf[nf][3];
        }
        rs0 += __shfl_xor_sync(0xffffffffu, rs0, 1);
        rs0 += __shfl_xor_sync(0xffffffffu, rs0, 2);
        rs1 += __shfl_xor_sync(0xffffffffu, rs1, 1);
        rs1 += __shfl_xor_sync(0xffffffffu, rs1, 2);

        l0 = l0 * sc0 + rs0;  m0 = mn0;
        l1 = l1 * sc1 + rs1;  m1 = mn1;
#pragma unroll
        for (int nf = 0; nf < 8; nf++) {
            o[nf][0] *= sc0;  o[nf][1] *= sc0;
            o[nf][2] *= sc1;  o[nf][3] *= sc1;
        }

#pragma unroll
        for (int nf = 0; nf < 8; nf++) {
            int c = nf * 8 + 2 * q4;
            float2 p01 = make_float2(__uint_as_float(f2tf32(sf[nf][0])),
                                     __uint_as_float(f2tf32(sf[nf][1])));
            float2 p23 = make_float2(__uint_as_float(f2tf32(sf[nf][2])),
                                     __uint_as_float(f2tf32(sf[nf][3])));
            *(float2*)&Pw[(g    ) * KVPAD + c] = p01;
            *(float2*)&Pw[(g + 8) * KVPAD + c] = p23;
        }
        __syncwarp();

#pragma unroll
        for (int ks = 0; ks < 8; ks++) {
            uint32_t a0 = __float_as_uint(Pw[(g    ) * KVPAD + ks * 8 + q4]);
            uint32_t a1 = __float_as_uint(Pw[(g + 8) * KVPAD + ks * 8 + q4]);
            uint32_t a2 = __float_as_uint(Pw[(g    ) * KVPAD + ks * 8 + q4 + 4]);
            uint32_t a3 = __float_as_uint(Pw[(g + 8) * KVPAD + ks * 8 + q4 + 4]);
#pragma unroll
            for (int nf = 0; nf < 8; nf++) {
                uint32_t b0 = __float_as_uint(Vs[(nf * 8 + g) * KVPAD + ks * 8 + q4]);
                uint32_t b1 = __float_as_uint(Vs[(nf * 8 + g) * KVPAD + ks * 8 + q4 + 4]);
                mma_tf32(o[nf], a0, a1, a2, a3, b0, b1);
            }
        }
        __syncthreads();
    }

    const int slot = b * SLOTS + idx;
    float* po = g_po + (size_t)slot * 4096;
    const int r0 = w * 16 + g;
    const int r1 = r0 + 8;
#pragma unroll
    for (int nf = 0; nf < 8; nf++) {
        int col = nf * 8 + 2 * q4;
        *(float2*)(po + r0 * 64 + col) = make_float2(o[nf][0], o[nf][1]);
        *(float2*)(po + r1 * 64 + col) = make_float2(o[nf][2], o[nf][3]);
    }
    if (q4 == 0) {
        g_pm[slot * 64 + r0] = m0;  g_pm[slot * 64 + r1] = m1;
        g_pl[slot * 64 + r0] = l0;  g_pl[slot * 64 + r1] = l1;
    }
}

// ---------------------------------------------------------------------------
// Merge: combine <=4 partials per query row. 32 threads per row, 8 rows/block.
// ---------------------------------------------------------------------------
__global__ __launch_bounds__(256) void merge_kernel(float* __restrict__ out)
{
    const int gid  = blockIdx.x * 8 + (threadIdx.x >> 5);
    const int lane = threadIdx.x & 31;
    const int b = gid >> 11;
    const int q = gid & 2047;
    const int qt    = q >> 6;
    const int rowin = q & 63;
    const int grp   = qt >> 3;
    const int nch   = grp + 1;
    const int base  = b * SLOTS + 4 * grp * (grp + 1) + (qt - 8 * grp) * (grp + 1);

    float mv[4];
    float M = -1e30f;
    for (int c = 0; c < nch; c++) {
        mv[c] = g_pm[(base + c) * 64 + rowin];
        M = fmaxf(M, mv[c]);
    }
    float L = 0.f, o0 = 0.f, o1 = 0.f;
    const int col = lane * 2;
    for (int c = 0; c < nch; c++) {
        float wgt = ex2f(mv[c] - M);
        L += wgt * g_pl[(base + c) * 64 + rowin];
        float2 ov = *(const float2*)(g_po + ((size_t)(base + c) * 64 + rowin) * 64 + col);
        o0 += wgt * ov.x;
        o1 += wgt * ov.y;
    }
    float inv = 1.f / L;
    *(float2*)(out + ((size_t)b * Tc + q) * Hc + col) = make_float2(o0 * inv, o1 * inv);
}

// ---------------------------------------------------------------------------
extern "C" void kernel_launch(void* const* d_in, const int* in_sizes, int n_in,
                              void* d_out, int out_size)
{
    (void)in_sizes; (void)n_in; (void)out_size;
    const float* x  = (const float*)d_in[0];
    const float* Wk = (const float*)d_in[1];
    const float* bk = (const float*)d_in[2];
    const float* Wq = (const float*)d_in[3];
    const float* bq = (const float*)d_in[4];
    const float* Wv = (const float*)d_in[5];
    const float* bv = (const float*)d_in[6];
    float* out = (float*)d_out;

    cudaFuncSetAttribute(proj_kernel, cudaFuncAttributeMaxDynamicSharedMemorySize, PSMEM);
    cudaFuncSetAttribute(attn_partial_kernel, cudaFuncAttributeMaxDynamicSharedMemorySize, ASMEM);

    proj_kernel<<<(Bc * Tc) / 128, 384, PSMEM>>>(x, Wq, Wk, Wv, bq, bk, bv);

    dim3 ag(SLOTS, Bc);
    attn_partial_kernel<<<ag, 128, ASMEM>>>();

    merge_kernel<<<(Bc * Tc) / 8, 256>>>(out);
}

// round 10
// speedup vs baseline: 4.0429x; 1.2318x over previous
#include <cuda_runtime.h>
#include <cuda_bf16.h>
#include <cstdint>

constexpr int Bc = 8;
constexpr int Tc = 2048;
constexpr int Dc = 1024;
constexpr int Hc = 64;

// q/k/v projections
__device__ float g_q[Bc * Tc * Hc];
__device__ float g_k[Bc * Tc * Hc];
__device__ float g_v[Bc * Tc * Hc];

// split-KV partials: 80 chunk-slots per batch (qtile i has ceil((i+1)/8) chunks)
constexpr int SLOTS = 80;
__device__ float g_po[Bc * SLOTS * 64 * 64];   // unnormalized O
__device__ float g_pm[Bc * SLOTS * 64];        // row max (exp2 space)
__device__ float g_pl[Bc * SLOTS * 64];        // row sum

__device__ __forceinline__ uint32_t f2tf32(float x) {
    uint32_t u;
    asm("cvt.rna.tf32.f32 %0, %1;" : "=r"(u) : "f"(x));
    return u;
}
__device__ __forceinline__ float ex2f(float x) {
    float y;
    asm("ex2.approx.ftz.f32 %0, %1;" : "=f"(y) : "f"(x));
    return y;
}
__device__ __forceinline__ void mma_tf32(float* c,
    uint32_t a0, uint32_t a1, uint32_t a2, uint32_t a3,
    uint32_t b0, uint32_t b1)
{
    asm volatile(
        "mma.sync.aligned.m16n8k8.row.col.f32.tf32.tf32.f32 "
        "{%0,%1,%2,%3}, {%4,%5,%6,%7}, {%8,%9}, {%0,%1,%2,%3};"
        : "+f"(c[0]), "+f"(c[1]), "+f"(c[2]), "+f"(c[3])
        : "r"(a0), "r"(a1), "r"(a2), "r"(a3), "r"(b0), "r"(b1));
}
__device__ __forceinline__ uint32_t smem_u32(const void* p) {
    return (uint32_t)__cvta_generic_to_shared(p);
}
__device__ __forceinline__ void cpa16(uint32_t dst, const void* src) {
    asm volatile("cp.async.ca.shared.global [%0], [%1], 16;" :: "r"(dst), "l"(src));
}
#define CP_COMMIT() asm volatile("cp.async.commit_group;")

// ---------------------------------------------------------------------------
// Fused projection, cp.async 3-stage pipeline, tf32 cvt at fragment load.
// (unchanged from round 9: 56 us, tensor 40%)
// ---------------------------------------------------------------------------
#define XPAD   36
#define WPAD   72
#define XS_F   (128 * XPAD)
#define STAGEF (XS_F + 3 * 32 * WPAD)
#define PSTAGES 3
#define PSMEM  (PSTAGES * STAGEF * 4)

__device__ __forceinline__ void proj_stage_async(
    uint32_t sb, const float* __restrict__ x,
    const float* const* Wp, int m0, int k0, int t)
{
    for (int idx = t; idx < 1024; idx += 384) {
        int row = idx >> 3;
        int c4  = (idx & 7) << 2;
        cpa16(sb + (uint32_t)(row * XPAD + c4) * 4,
              x + (size_t)(m0 + row) * Dc + k0 + c4);
    }
#pragma unroll
    for (int i = 0; i < 4; i++) {
        int idx = t + i * 384;
        int p   = idx >> 9;
        int rem = idx & 511;
        int row = rem >> 4;
        int c4  = (rem & 15) << 2;
        cpa16(sb + (uint32_t)(XS_F + (p * 32 + row) * WPAD + c4) * 4,
              Wp[p] + (size_t)(k0 + row) * Hc + c4);
    }
}

__global__ __launch_bounds__(384, 1) void proj_kernel(
    const float* __restrict__ x,
    const float* __restrict__ Wq, const float* __restrict__ Wk, const float* __restrict__ Wv,
    const float* __restrict__ bq, const float* __restrict__ bk, const float* __restrict__ bv)
{
    extern __shared__ float psm[];
    const float* Wp[3] = { Wq, Wk, Wv };

    const int t    = threadIdx.x;
    const int w    = t >> 5;
    const int p    = w >> 2;
    const int ww   = w & 3;
    const int lane = t & 31;
    const int g    = lane >> 2;
    const int q4   = lane & 3;
    const int m0   = blockIdx.x * 128;

    const uint32_t sb = smem_u32(psm);

    float acc[2][8][4];
#pragma unroll
    for (int i = 0; i < 2; i++)
#pragma unroll
        for (int nf = 0; nf < 8; nf++)
#pragma unroll
            for (int j = 0; j < 4; j++) acc[i][nf][j] = 0.f;

    proj_stage_async(sb,              x, Wp, m0, 0,  t);
    CP_COMMIT();
    proj_stage_async(sb + STAGEF * 4, x, Wp, m0, 32, t);
    CP_COMMIT();

    for (int it = 0; it < 32; it++) {
        if (it < 30) {
            proj_stage_async(sb + (uint32_t)((it + 2) % 3) * STAGEF * 4,
                             x, Wp, m0, (it + 2) * 32, t);
            CP_COMMIT();
            asm volatile("cp.async.wait_group 2;");
        } else if (it == 30) {
            asm volatile("cp.async.wait_group 1;");
        } else {
            asm volatile("cp.async.wait_group 0;");
        }
        __syncthreads();

        const float* Xs = psm + (it % 3) * STAGEF;
        const float* Ws = Xs + XS_F + p * 32 * WPAD;

#pragma unroll
        for (int ks = 0; ks < 4; ks++) {
            const int kc = ks * 8 + q4;
            uint32_t a[2][4];
#pragma unroll
            for (int i = 0; i < 2; i++) {
                const int r = ww * 32 + i * 16 + g;
                a[i][0] = f2tf32(Xs[(r    ) * XPAD + kc]);
                a[i][1] = f2tf32(Xs[(r + 8) * XPAD + kc]);
                a[i][2] = f2tf32(Xs[(r    ) * XPAD + kc + 4]);
                a[i][3] = f2tf32(Xs[(r + 8) * XPAD + kc + 4]);
            }
#pragma unroll
            for (int nf = 0; nf < 8; nf++) {
                uint32_t b0 = f2tf32(Ws[(kc    ) * WPAD + nf * 8 + g]);
                uint32_t b1 = f2tf32(Ws[(kc + 4) * WPAD + nf * 8 + g]);
                mma_tf32(acc[0][nf], a[0][0], a[0][1], a[0][2], a[0][3], b0, b1);
                mma_tf32(acc[1][nf], a[1][0], a[1][1], a[1][2], a[1][3], b0, b1);
            }
        }
        __syncthreads();
    }

    const float* biases[3] = { bq, bk, bv };
    float* outs[3] = { g_q, g_k, g_v };
    float* out = outs[p];
    const float* bias = biases[p];
#pragma unroll
    for (int i = 0; i < 2; i++) {
        const int r0 = m0 + ww * 32 + i * 16 + g;
#pragma unroll
        for (int nf = 0; nf < 8; nf++) {
            int col = nf * 8 + 2 * q4;
            float b0 = bias[col], b1 = bias[col + 1];
            float2 v0 = make_float2(acc[i][nf][0] + b0, acc[i][nf][1] + b1);
            float2 v1 = make_float2(acc[i][nf][2] + b0, acc[i][nf][3] + b1);
            *(float2*)(out + (size_t)r0 * Hc + col)       = v0;
            *(float2*)(out + (size_t)(r0 + 8) * Hc + col) = v1;
        }
    }
}

// ---------------------------------------------------------------------------
// Attention partials, v2:
//  - cp.async 2-stage staging of K and V, RAW natural layout (no transpose,
//    no cvt at stage). K row-stride 68 (QK B-load banks 4g+q4: conflict-free),
//    V row-stride 72 (PV B-load banks 8q4+8nf+g: conflict-free).
//  - PV A-fragments built from S accumulators via warp shuffles (no P smem).
//  - smem 70 KB -> 3 CTAs/SM.
// ---------------------------------------------------------------------------
#define KPAD 68
#define VPAD 72
#define KTILE (64 * KPAD)            // 4352 floats
#define VTILE (64 * VPAD)            // 4608 floats
#define STF   (KTILE + VTILE)        // 8960 floats per stage
#define ASMEM (2 * STF * 4)          // 71680 bytes

__device__ __forceinline__ void attn_stage_async(
    uint32_t sb, const float* __restrict__ kb, const float* __restrict__ vb,
    int kn0, int t)
{
    // K tile [64][64] -> [64][KPAD]: 1024 16B chunks
#pragma unroll
    for (int i = 0; i < 8; i++) {
        int idx = t + i * 128;
        int row = idx >> 4;
        int c4  = (idx & 15) << 2;
        cpa16(sb + (uint32_t)(row * KPAD + c4) * 4,
              kb + (size_t)(kn0 + row) * Hc + c4);
    }
    // V tile [64][64] -> [64][VPAD]: 1024 16B chunks
#pragma unroll
    for (int i = 0; i < 8; i++) {
        int idx = t + i * 128;
        int row = idx >> 4;
        int c4  = (idx & 15) << 2;
        cpa16(sb + (uint32_t)(KTILE + row * VPAD + c4) * 4,
              vb + (size_t)(kn0 + row) * Hc + c4);
    }
}

__global__ __launch_bounds__(128) void attn_partial_kernel()
{
    extern __shared__ float sm[];
    const uint32_t sb = smem_u32(sm);

    const int b   = blockIdx.y;
    const int idx = (int)(gridDim.x - 1 - blockIdx.x);   // heavy chunks first

    int qt = 0, ch = 0;
#pragma unroll
    for (int gg = 3; gg >= 0; gg--) {
        int s = 4 * gg * (gg + 1);
        if (idx >= s) { qt = 8 * gg + (idx - s) / (gg + 1); ch = (idx - s) % (gg + 1); break; }
    }
    const int q0  = qt * 64;
    const int kt0 = ch * 8;
    const int kt1 = min(kt0 + 8, qt + 1);

    const int t    = threadIdx.x;
    const int w    = t >> 5;
    const int lane = t & 31;
    const int g    = lane >> 2;
    const int q4   = lane & 3;

    const float* qb = g_q + (size_t)b * Tc * Hc;
    const float* kb = g_k + (size_t)b * Tc * Hc;
    const float* vb = g_v + (size_t)b * Tc * Hc;

    // kick off first stage before doing Q loads (overlap)
    attn_stage_async(sb, kb, vb, kt0 * 64, t);
    CP_COMMIT();

    const float SC = 0.125f * 1.44269504f;
    uint32_t qa[8][4];
    {
        const float* r0 = qb + (size_t)(q0 + w * 16 + g) * Hc;
        const float* r1 = r0 + 8 * Hc;
#pragma unroll
        for (int ks = 0; ks < 8; ks++) {
            qa[ks][0] = f2tf32(r0[ks * 8 + q4] * SC);
            qa[ks][1] = f2tf32(r1[ks * 8 + q4] * SC);
            qa[ks][2] = f2tf32(r0[ks * 8 + q4 + 4] * SC);
            qa[ks][3] = f2tf32(r1[ks * 8 + q4 + 4] * SC);
        }
    }

    float o[8][4];
#pragma unroll
    for (int nf = 0; nf < 8; nf++)
#pragma unroll
        for (int j = 0; j < 4; j++) o[nf][j] = 0.f;
    float m0 = -1e30f, m1 = -1e30f, l0 = 0.f, l1 = 0.f;

    // shuffle-permute constants for S-accum -> A-frag
    const int srcA = 4 * g + (q4 >> 1);
    const int srcB = srcA + 2;
    const bool odd = (q4 & 1);

    for (int kt = kt0; kt < kt1; kt++) {
        const int buf = (kt - kt0) & 1;
        if (kt + 1 < kt1) {
            attn_stage_async(sb + (uint32_t)(buf ^ 1) * STF * 4, kb, vb, (kt + 1) * 64, t);
            CP_COMMIT();
            asm volatile("cp.async.wait_group 1;");
        } else {
            asm volatile("cp.async.wait_group 0;");
        }
        __syncthreads();

        const float* Ks = sm + buf * STF;          // [kv][KPAD] raw f32
        const float* Vs = Ks + KTILE;              // [kv][VPAD] raw f32
        const int kn0 = kt * 64;

        // S = Q @ K^T
        float sf[8][4];
#pragma unroll
        for (int nf = 0; nf < 8; nf++) {
            sf[nf][0] = sf[nf][1] = sf[nf][2] = sf[nf][3] = 0.f;
#pragma unroll
            for (int ks = 0; ks < 8; ks++) {
                uint32_t b0 = f2tf32(Ks[(nf * 8 + g) * KPAD + ks * 8 + q4]);
                uint32_t b1 = f2tf32(Ks[(nf * 8 + g) * KPAD + ks * 8 + q4 + 4]);
                mma_tf32(sf[nf], qa[ks][0], qa[ks][1], qa[ks][2], qa[ks][3], b0, b1);
            }
        }

        if (kt == qt) {   // diagonal tile: causal mask
            const int r0 = q0 + w * 16 + g;
            const int r1 = r0 + 8;
#pragma unroll
            for (int nf = 0; nf < 8; nf++) {
                int c0 = kn0 + nf * 8 + 2 * q4;
                if (c0     > r0) sf[nf][0] = -1e30f;
                if (c0 + 1 > r0) sf[nf][1] = -1e30f;
                if (c0     > r1) sf[nf][2] = -1e30f;
                if (c0 + 1 > r1) sf[nf][3] = -1e30f;
            }
        }

        // online softmax (exp2 space)
        float mx0 = -1e30f, mx1 = -1e30f;
#pragma unroll
        for (int nf = 0; nf < 8; nf++) {
            mx0 = fmaxf(mx0, fmaxf(sf[nf][0], sf[nf][1]));
            mx1 = fmaxf(mx1, fmaxf(sf[nf][2], sf[nf][3]));
        }
        mx0 = fmaxf(mx0, __shfl_xor_sync(0xffffffffu, mx0, 1));
        mx0 = fmaxf(mx0, __shfl_xor_sync(0xffffffffu, mx0, 2));
        mx1 = fmaxf(mx1, __shfl_xor_sync(0xffffffffu, mx1, 1));
        mx1 = fmaxf(mx1, __shfl_xor_sync(0xffffffffu, mx1, 2));

        float mn0 = fmaxf(m0, mx0), mn1 = fmaxf(m1, mx1);
        float sc0 = ex2f(m0 - mn0), sc1 = ex2f(m1 - mn1);

        float rs0 = 0.f, rs1 = 0.f;
#pragma unroll
        for (int nf = 0; nf < 8; nf++) {
            sf[nf][0] = ex2f(sf[nf][0] - mn0);
            sf[nf][1] = ex2f(sf[nf][1] - mn0);
            sf[nf][2] = ex2f(sf[nf][2] - mn1);
            sf[nf][3] = ex2f(sf[nf][3] - mn1);
            rs0 += sf[nf][0] + sf[nf][1];
            rs1 += sf[nf][2] + sf[nf][3];
        }
        rs0 += __shfl_xor_sync(0xffffffffu, rs0, 1);
        rs0 += __shfl_xor_sync(0xffffffffu, rs0, 2);
        rs1 += __shfl_xor_sync(0xffffffffu, rs1, 1);
        rs1 += __shfl_xor_sync(0xffffffffu, rs1, 2);

        l0 = l0 * sc0 + rs0;  m0 = mn0;
        l1 = l1 * sc1 + rs1;  m1 = mn1;
#pragma unroll
        for (int nf = 0; nf < 8; nf++) {
            o[nf][0] *= sc0;  o[nf][1] *= sc0;
            o[nf][2] *= sc1;  o[nf][3] *= sc1;
        }

        // O += P @ V : A-frags from S accumulators via shuffles (no smem P)
#pragma unroll
        for (int ks = 0; ks < 8; ks++) {
            float s0A = __shfl_sync(0xffffffffu, sf[ks][0], srcA);
            float s1A = __shfl_sync(0xffffffffu, sf[ks][1], srcA);
            float s2A = __shfl_sync(0xffffffffu, sf[ks][2], srcA);
            float s3A = __shfl_sync(0xffffffffu, sf[ks][3], srcA);
            float s0B = __shfl_sync(0xffffffffu, sf[ks][0], srcB);
            float s1B = __shfl_sync(0xffffffffu, sf[ks][1], srcB);
            float s2B = __shfl_sync(0xffffffffu, sf[ks][2], srcB);
            float s3B = __shfl_sync(0xffffffffu, sf[ks][3], srcB);
            uint32_t a0 = f2tf32(odd ? s1A : s0A);
            uint32_t a1 = f2tf32(odd ? s3A : s2A);
            uint32_t a2 = f2tf32(odd ? s1B : s0B);
            uint32_t a3 = f2tf32(odd ? s3B : s2B);
#pragma unroll
            for (int nf = 0; nf < 8; nf++) {
                uint32_t b0 = f2tf32(Vs[(ks * 8 + q4    ) * VPAD + nf * 8 + g]);
                uint32_t b1 = f2tf32(Vs[(ks * 8 + q4 + 4) * VPAD + nf * 8 + g]);
                mma_tf32(o[nf], a0, a1, a2, a3, b0, b1);
            }
        }
        __syncthreads();   // all warps done with buf before it is re-staged
    }

    // write partial (unnormalized O, m, l)
    const int slot = b * SLOTS + idx;
    float* po = g_po + (size_t)slot * 4096;
    const int r0 = w * 16 + g;
    const int r1 = r0 + 8;
#pragma unroll
    for (int nf = 0; nf < 8; nf++) {
        int col = nf * 8 + 2 * q4;
        *(float2*)(po + r0 * 64 + col) = make_float2(o[nf][0], o[nf][1]);
        *(float2*)(po + r1 * 64 + col) = make_float2(o[nf][2], o[nf][3]);
    }
    if (q4 == 0) {
        g_pm[slot * 64 + r0] = m0;  g_pm[slot * 64 + r1] = m1;
        g_pl[slot * 64 + r0] = l0;  g_pl[slot * 64 + r1] = l1;
    }
}

// ---------------------------------------------------------------------------
// Merge: combine <=4 partials per query row. 32 threads per row, 8 rows/block.
// ---------------------------------------------------------------------------
__global__ __launch_bounds__(256) void merge_kernel(float* __restrict__ out)
{
    const int gid  = blockIdx.x * 8 + (threadIdx.x >> 5);
    const int lane = threadIdx.x & 31;
    const int b = gid >> 11;
    const int q = gid & 2047;
    const int qt    = q >> 6;
    const int rowin = q & 63;
    const int grp   = qt >> 3;
    const int nch   = grp + 1;
    const int base  = b * SLOTS + 4 * grp * (grp + 1) + (qt - 8 * grp) * (grp + 1);

    float mv[4];
    float M = -1e30f;
    for (int c = 0; c < nch; c++) {
        mv[c] = g_pm[(base + c) * 64 + rowin];
        M = fmaxf(M, mv[c]);
    }
    float L = 0.f, o0 = 0.f, o1 = 0.f;
    const int col = lane * 2;
    for (int c = 0; c < nch; c++) {
        float wgt = ex2f(mv[c] - M);
        L += wgt * g_pl[(base + c) * 64 + rowin];
        float2 ov = *(const float2*)(g_po + ((size_t)(base + c) * 64 + rowin) * 64 + col);
        o0 += wgt * ov.x;
        o1 += wgt * ov.y;
    }
    float inv = 1.f / L;
    *(float2*)(out + ((size_t)b * Tc + q) * Hc + col) = make_float2(o0 * inv, o1 * inv);
}

// ---------------------------------------------------------------------------
extern "C" void kernel_launch(void* const* d_in, const int* in_sizes, int n_in,
                              void* d_out, int out_size)
{
    (void)in_sizes; (void)n_in; (void)out_size;
    const float* x  = (const float*)d_in[0];
    const float* Wk = (const float*)d_in[1];
    const float* bk = (const float*)d_in[2];
    const float* Wq = (const float*)d_in[3];
    const float* bq = (const float*)d_in[4];
    const float* Wv = (const float*)d_in[5];
    const float* bv = (const float*)d_in[6];
    float* out = (float*)d_out;

    cudaFuncSetAttribute(proj_kernel, cudaFuncAttributeMaxDynamicSharedMemorySize, PSMEM);
    cudaFuncSetAttribute(attn_partial_kernel, cudaFuncAttributeMaxDynamicSharedMemorySize, ASMEM);

    proj_kernel<<<(Bc * Tc) / 128, 384, PSMEM>>>(x, Wq, Wk, Wv, bq, bk, bv);

    dim3 ag(SLOTS, Bc);
    attn_partial_kernel<<<ag, 128, ASMEM>>>();

    merge_kernel<<<(Bc * Tc) / 8, 256>>>(out);
}

// round 12
// speedup vs baseline: 4.4183x; 1.0929x over previous
#include <cuda_runtime.h>
#include <cuda_bf16.h>
#include <cstdint>

constexpr int Bc = 8;
constexpr int Tc = 2048;
constexpr int Dc = 1024;
constexpr int Hc = 64;

// q/k/v projections (stored tf32-rounded f32)
__device__ float g_q[Bc * Tc * Hc];
__device__ float g_k[Bc * Tc * Hc];
__device__ float g_v[Bc * Tc * Hc];

// tf32-rounded copies of the weights
__device__ float g_wq[Dc * Hc];
__device__ float g_wk[Dc * Hc];
__device__ float g_wv[Dc * Hc];

// split-KV partials: 80 chunk-slots per batch
constexpr int SLOTS = 80;
__device__ float g_po[Bc * SLOTS * 64 * 64];
__device__ float g_pm[Bc * SLOTS * 64];
__device__ float g_pl[Bc * SLOTS * 64];

__device__ __forceinline__ uint32_t f2tf32(float x) {
    uint32_t u;
    asm("cvt.rna.tf32.f32 %0, %1;" : "=r"(u) : "f"(x));
    return u;
}
__device__ __forceinline__ float ex2f(float x) {
    float y;
    asm("ex2.approx.ftz.f32 %0, %1;" : "=f"(y) : "f"(x));
    return y;
}
__device__ __forceinline__ void mma_tf32(float* c,
    uint32_t a0, uint32_t a1, uint32_t a2, uint32_t a3,
    uint32_t b0, uint32_t b1)
{
    asm volatile(
        "mma.sync.aligned.m16n8k8.row.col.f32.tf32.tf32.f32 "
        "{%0,%1,%2,%3}, {%4,%5,%6,%7}, {%8,%9}, {%0,%1,%2,%3};"
        : "+f"(c[0]), "+f"(c[1]), "+f"(c[2]), "+f"(c[3])
        : "r"(a0), "r"(a1), "r"(a2), "r"(a3), "r"(b0), "r"(b1));
}
__device__ __forceinline__ uint32_t smem_u32(const void* p) {
    return (uint32_t)__cvta_generic_to_shared(p);
}
__device__ __forceinline__ void cpa16(uint32_t dst, const void* src) {
    asm volatile("cp.async.ca.shared.global [%0], [%1], 16;" :: "r"(dst), "l"(src));
}
#define CP_COMMIT() asm volatile("cp.async.commit_group;")

// ---------------------------------------------------------------------------
// W prepass: tf32-round the three weight matrices into scratch. ~768 KB.
// ---------------------------------------------------------------------------
__global__ __launch_bounds__(256) void prep_w_kernel(
    const float* __restrict__ Wq, const float* __restrict__ Wk, const float* __restrict__ Wv)
{
    const int idx = blockIdx.x * 256 + threadIdx.x;       // float4 index
    const int p   = idx / (Dc * Hc / 4);
    const int r   = idx % (Dc * Hc / 4);
    const float* src = (p == 0) ? Wq : (p == 1) ? Wk : Wv;
    float* dst = (p == 0) ? g_wq : (p == 1) ? g_wk : g_wv;
    float4 v = *(const float4*)(src + r * 4);
    float4 o = make_float4(__uint_as_float(f2tf32(v.x)), __uint_as_float(f2tf32(v.y)),
                           __uint_as_float(f2tf32(v.z)), __uint_as_float(f2tf32(v.w)));
    *(float4*)(dst + r * 4) = o;
}

// ---------------------------------------------------------------------------
// Fused projection, cp.async 3-stage pipeline.
// B (weights) pre-rounded -> raw fragment loads. A (x) cvt at fragment load.
// Epilogue writes tf32-rounded q/k/v.
// ---------------------------------------------------------------------------
#define XPAD   36
#define WPAD   72
#define XS_F   (128 * XPAD)
#define STAGEF (XS_F + 3 * 32 * WPAD)
#define PSTAGES 3
#define PSMEM  (PSTAGES * STAGEF * 4)

__device__ __forceinline__ void proj_stage_async(
    uint32_t sb, const float* __restrict__ x,
    const float* const* Wp, int m0, int k0, int t)
{
    for (int idx = t; idx < 1024; idx += 384) {
        int row = idx >> 3;
        int c4  = (idx & 7) << 2;
        cpa16(sb + (uint32_t)(row * XPAD + c4) * 4,
              x + (size_t)(m0 + row) * Dc + k0 + c4);
    }
#pragma unroll
    for (int i = 0; i < 4; i++) {
        int idx = t + i * 384;
        int p   = idx >> 9;
        int rem = idx & 511;
        int row = rem >> 4;
        int c4  = (rem & 15) << 2;
        cpa16(sb + (uint32_t)(XS_F + (p * 32 + row) * WPAD + c4) * 4,
              Wp[p] + (size_t)(k0 + row) * Hc + c4);
    }
}

__global__ __launch_bounds__(384, 1) void proj_kernel(
    const float* __restrict__ x,
    const float* __restrict__ bq, const float* __restrict__ bk, const float* __restrict__ bv)
{
    extern __shared__ float psm[];
    const float* Wp[3] = { g_wq, g_wk, g_wv };

    const int t    = threadIdx.x;
    const int w    = t >> 5;
    const int p    = w >> 2;
    const int ww   = w & 3;
    const int lane = t & 31;
    const int g    = lane >> 2;
    const int q4   = lane & 3;
    const int m0   = blockIdx.x * 128;

    const uint32_t sb = smem_u32(psm);

    float acc[2][8][4];
#pragma unroll
    for (int i = 0; i < 2; i++)
#pragma unroll
        for (int nf = 0; nf < 8; nf++)
#pragma unroll
            for (int j = 0; j < 4; j++) acc[i][nf][j] = 0.f;

    proj_stage_async(sb,              x, Wp, m0, 0,  t);
    CP_COMMIT();
    proj_stage_async(sb + STAGEF * 4, x, Wp, m0, 32, t);
    CP_COMMIT();

    for (int it = 0; it < 32; it++) {
        if (it < 30) {
            proj_stage_async(sb + (uint32_t)((it + 2) % 3) * STAGEF * 4,
                             x, Wp, m0, (it + 2) * 32, t);
            CP_COMMIT();
            asm volatile("cp.async.wait_group 2;");
        } else if (it == 30) {
            asm volatile("cp.async.wait_group 1;");
        } else {
            asm volatile("cp.async.wait_group 0;");
        }
        __syncthreads();

        const float* Xs = psm + (it % 3) * STAGEF;
        const float* Ws = Xs + XS_F + p * 32 * WPAD;

#pragma unroll
        for (int ks = 0; ks < 4; ks++) {
            const int kc = ks * 8 + q4;
            uint32_t a[2][4];
#pragma unroll
            for (int i = 0; i < 2; i++) {
                const int r = ww * 32 + i * 16 + g;
                a[i][0] = f2tf32(Xs[(r    ) * XPAD + kc]);
                a[i][1] = f2tf32(Xs[(r + 8) * XPAD + kc]);
                a[i][2] = f2tf32(Xs[(r    ) * XPAD + kc + 4]);
                a[i][3] = f2tf32(Xs[(r + 8) * XPAD + kc + 4]);
            }
#pragma unroll
            for (int nf = 0; nf < 8; nf++) {
                uint32_t b0 = __float_as_uint(Ws[(kc    ) * WPAD + nf * 8 + g]);  // raw: pre-rounded
                uint32_t b1 = __float_as_uint(Ws[(kc + 4) * WPAD + nf * 8 + g]);
                mma_tf32(acc[0][nf], a[0][0], a[0][1], a[0][2], a[0][3], b0, b1);
                mma_tf32(acc[1][nf], a[1][0], a[1][1], a[1][2], a[1][3], b0, b1);
            }
        }
        __syncthreads();
    }

    const float* biases[3] = { bq, bk, bv };
    float* outs[3] = { g_q, g_k, g_v };
    float* out = outs[p];
    const float* bias = biases[p];
#pragma unroll
    for (int i = 0; i < 2; i++) {
        const int r0 = m0 + ww * 32 + i * 16 + g;
#pragma unroll
        for (int nf = 0; nf < 8; nf++) {
            int col = nf * 8 + 2 * q4;
            float b0 = bias[col], b1 = bias[col + 1];
            // write tf32-rounded so attention can skip all fragment cvts
            float2 v0 = make_float2(__uint_as_float(f2tf32(acc[i][nf][0] + b0)),
                                    __uint_as_float(f2tf32(acc[i][nf][1] + b1)));
            float2 v1 = make_float2(__uint_as_float(f2tf32(acc[i][nf][2] + b0)),
                                    __uint_as_float(f2tf32(acc[i][nf][3] + b1)));
            *(float2*)(out + (size_t)r0 * Hc + col)       = v0;
            *(float2*)(out + (size_t)(r0 + 8) * Hc + col) = v1;
        }
    }
}

// ---------------------------------------------------------------------------
// Attention partials: cp.async staging, raw (pre-rounded) K/V fragment loads,
// shuffle-built PV A-fragments. No cvt in either MMA inner loop.
// ---------------------------------------------------------------------------
#define KPAD 68
#define VPAD 72
#define KTILE (64 * KPAD)
#define VTILE (64 * VPAD)
#define STF   (KTILE + VTILE)
#define ASMEM (2 * STF * 4)

__device__ __forceinline__ void attn_stage_async(
    uint32_t sb, const float* __restrict__ kb, const float* __restrict__ vb,
    int kn0, int t)
{
#pragma unroll
    for (int i = 0; i < 8; i++) {
        int idx = t + i * 128;
        int row = idx >> 4;
        int c4  = (idx & 15) << 2;
        cpa16(sb + (uint32_t)(row * KPAD + c4) * 4,
              kb + (size_t)(kn0 + row) * Hc + c4);
    }
#pragma unroll
    for (int i = 0; i < 8; i++) {
        int idx = t + i * 128;
        int row = idx >> 4;
        int c4  = (idx & 15) << 2;
        cpa16(sb + (uint32_t)(KTILE + row * VPAD + c4) * 4,
              vb + (size_t)(kn0 + row) * Hc + c4);
    }
}

__global__ __launch_bounds__(128) void attn_partial_kernel()
{
    extern __shared__ float sm[];
    const uint32_t sb = smem_u32(sm);

    const int b   = blockIdx.y;
    const int idx = (int)(gridDim.x - 1 - blockIdx.x);

    int qt = 0, ch = 0;
#pragma unroll
    for (int gg = 3; gg >= 0; gg--) {
        int s = 4 * gg * (gg + 1);
        if (idx >= s) { qt = 8 * gg + (idx - s) / (gg + 1); ch = (idx - s) % (gg + 1); break; }
    }
    const int q0  = qt * 64;
    const int kt0 = ch * 8;
    const int kt1 = min(kt0 + 8, qt + 1);

    const int t    = threadIdx.x;
    const int w    = t >> 5;
    const int lane = t & 31;
    const int g    = lane >> 2;
    const int q4   = lane & 3;

    const float* qb = g_q + (size_t)b * Tc * Hc;
    const float* kb = g_k + (size_t)b * Tc * Hc;
    const float* vb = g_v + (size_t)b * Tc * Hc;

    attn_stage_async(sb, kb, vb, kt0 * 64, t);
    CP_COMMIT();

    const float SC = 0.125f * 1.44269504f;
    uint32_t qa[8][4];
    {
        const float* r0 = qb + (size_t)(q0 + w * 16 + g) * Hc;
        const float* r1 = r0 + 8 * Hc;
#pragma unroll
        for (int ks = 0; ks < 8; ks++) {
            qa[ks][0] = f2tf32(r0[ks * 8 + q4] * SC);
            qa[ks][1] = f2tf32(r1[ks * 8 + q4] * SC);
            qa[ks][2] = f2tf32(r0[ks * 8 + q4 + 4] * SC);
            qa[ks][3] = f2tf32(r1[ks * 8 + q4 + 4] * SC);
        }
    }

    float o[8][4];
#pragma unroll
    for (int nf = 0; nf < 8; nf++)
#pragma unroll
        for (int j = 0; j < 4; j++) o[nf][j] = 0.f;
    float m0 = -1e30f, m1 = -1e30f, l0 = 0.f, l1 = 0.f;

    const int srcA = 4 * g + (q4 >> 1);
    const int srcB = srcA + 2;
    const bool odd = (q4 & 1);

    for (int kt = kt0; kt < kt1; kt++) {
        const int buf = (kt - kt0) & 1;
        if (kt + 1 < kt1) {
            attn_stage_async(sb + (uint32_t)(buf ^ 1) * STF * 4, kb, vb, (kt + 1) * 64, t);
            CP_COMMIT();
            asm volatile("cp.async.wait_group 1;");
        } else {
            asm volatile("cp.async.wait_group 0;");
        }
        __syncthreads();

        const float* Ks = sm + buf * STF;
        const float* Vs = Ks + KTILE;
        const int kn0 = kt * 64;

        // S = Q @ K^T  (K fragments raw: values pre-rounded by proj)
        float sf[8][4];
#pragma unroll
        for (int nf = 0; nf < 8; nf++) {
            sf[nf][0] = sf[nf][1] = sf[nf][2] = sf[nf][3] = 0.f;
#pragma unroll
            for (int ks = 0; ks < 8; ks++) {
                uint32_t b0 = __float_as_uint(Ks[(nf * 8 + g) * KPAD + ks * 8 + q4]);
                uint32_t b1 = __float_as_uint(Ks[(nf * 8 + g) * KPAD + ks * 8 + q4 + 4]);
                mma_tf32(sf[nf], qa[ks][0], qa[ks][1], qa[ks][2], qa[ks][3], b0, b1);
            }
        }

        if (kt == qt) {
            const int r0 = q0 + w * 16 + g;
            const int r1 = r0 + 8;
#pragma unroll
            for (int nf = 0; nf < 8; nf++) {
                int c0 = kn0 + nf * 8 + 2 * q4;
                if (c0     > r0) sf[nf][0] = -1e30f;
                if (c0 + 1 > r0) sf[nf][1] = -1e30f;
                if (c0     > r1) sf[nf][2] = -1e30f;
                if (c0 + 1 > r1) sf[nf][3] = -1e30f;
            }
        }

        float mx0 = -1e30f, mx1 = -1e30f;
#pragma unroll
        for (int nf = 0; nf < 8; nf++) {
            mx0 = fmaxf(mx0, fmaxf(sf[nf][0], sf[nf][1]));
            mx1 = fmaxf(mx1, fmaxf(sf[nf][2], sf[nf][3]));
        }
        mx0 = fmaxf(mx0, __shfl_xor_sync(0xffffffffu, mx0, 1));
        mx0 = fmaxf(mx0, __shfl_xor_sync(0xffffffffu, mx0, 2));
        mx1 = fmaxf(mx1, __shfl_xor_sync(0xffffffffu, mx1, 1));
        mx1 = fmaxf(mx1, __shfl_xor_sync(0xffffffffu, mx1, 2));

        float mn0 = fmaxf(m0, mx0), mn1 = fmaxf(m1, mx1);
        float sc0 = ex2f(m0 - mn0), sc1 = ex2f(m1 - mn1);

        float rs0 = 0.f, rs1 = 0.f;
#pragma unroll
        for (int nf = 0; nf < 8; nf++) {
            sf[nf][0] = ex2f(sf[nf][0] - mn0);
            sf[nf][1] = ex2f(sf[nf][1] - mn0);
            sf[nf][2] = ex2f(sf[nf][2] - mn1);
            sf[nf][3] = ex2f(sf[nf][3] - mn1);
            rs0 += sf[nf][0] + sf[nf][1];
            rs1 += sf[nf][2] + sf[nf][3];
        }
        rs0 += __shfl_xor_sync(0xffffffffu, rs0, 1);
        rs0 += __shfl_xor_sync(0xffffffffu, rs0, 2);
        rs1 += __shfl_xor_sync(0xffffffffu, rs1, 1);
        rs1 += __shfl_xor_sync(0xffffffffu, rs1, 2);

        l0 = l0 * sc0 + rs0;  m0 = mn0;
        l1 = l1 * sc1 + rs1;  m1 = mn1;
#pragma unroll
        for (int nf = 0; nf < 8; nf++) {
            o[nf][0] *= sc0;  o[nf][1] *= sc0;
            o[nf][2] *= sc1;  o[nf][3] *= sc1;
        }

        // O += P @ V (P via shuffles; V fragments raw)
#pragma unroll
        for (int ks = 0; ks < 8; ks++) {
            float s0A = __shfl_sync(0xffffffffu, sf[ks][0], srcA);
            float s1A = __shfl_sync(0xffffffffu, sf[ks][1], srcA);
            float s2A = __shfl_sync(0xffffffffu, sf[ks][2], srcA);
            float s3A = __shfl_sync(0xffffffffu, sf[ks][3], srcA);
            float s0B = __shfl_sync(0xffffffffu, sf[ks][0], srcB);
            float s1B = __shfl_sync(0xffffffffu, sf[ks][1], srcB);
            float s2B = __shfl_sync(0xffffffffu, sf[ks][2], srcB);
            float s3B = __shfl_sync(0xffffffffu, sf[ks][3], srcB);
            uint32_t a0 = f2tf32(odd ? s1A : s0A);
            uint32_t a1 = f2tf32(odd ? s3A : s2A);
            uint32_t a2 = f2tf32(odd ? s1B : s0B);
            uint32_t a3 = f2tf32(odd ? s3B : s2B);
#pragma unroll
            for (int nf = 0; nf < 8; nf++) {
                uint32_t b0 = __float_as_uint(Vs[(ks * 8 + q4    ) * VPAD + nf * 8 + g]);
                uint32_t b1 = __float_as_uint(Vs[(ks * 8 + q4 + 4) * VPAD + nf * 8 + g]);
                mma_tf32(o[nf], a0, a1, a2, a3, b0, b1);
            }
        }
        __syncthreads();
    }

    const int slot = b * SLOTS + idx;
    float* po = g_po + (size_t)slot * 4096;
    const int r0 = w * 16 + g;
    const int r1 = r0 + 8;
#pragma unroll
    for (int nf = 0; nf < 8; nf++) {
        int col = nf * 8 + 2 * q4;
        *(float2*)(po + r0 * 64 + col) = make_float2(o[nf][0], o[nf][1]);
        *(float2*)(po + r1 * 64 + col) = make_float2(o[nf][2], o[nf][3]);
    }
    if (q4 == 0) {
        g_pm[slot * 64 + r0] = m0;  g_pm[slot * 64 + r1] = m1;
        g_pl[slot * 64 + r0] = l0;  g_pl[slot * 64 + r1] = l1;
    }
}

// ---------------------------------------------------------------------------
// Merge (unchanged)
// ---------------------------------------------------------------------------
__global__ __launch_bounds__(256) void merge_kernel(float* __restrict__ out)
{
    const int gid  = blockIdx.x * 8 + (threadIdx.x >> 5);
    const int lane = threadIdx.x & 31;
    const int b = gid >> 11;
    const int q = gid & 2047;
    const int qt    = q >> 6;
    const int rowin = q & 63;
    const int grp   = qt >> 3;
    const int nch   = grp + 1;
    const int base  = b * SLOTS + 4 * grp * (grp + 1) + (qt - 8 * grp) * (grp + 1);

    float mv[4];
    float M = -1e30f;
    for (int c = 0; c < nch; c++) {
        mv[c] = g_pm[(base + c) * 64 + rowin];
        M = fmaxf(M, mv[c]);
    }
    float L = 0.f, o0 = 0.f, o1 = 0.f;
    const int col = lane * 2;
    for (int c = 0; c < nch; c++) {
        float wgt = ex2f(mv[c] - M);
        L += wgt * g_pl[(base + c) * 64 + rowin];
        float2 ov = *(const float2*)(g_po + ((size_t)(base + c) * 64 + rowin) * 64 + col);
        o0 += wgt * ov.x;
        o1 += wgt * ov.y;
    }
    float inv = 1.f / L;
    *(float2*)(out + ((size_t)b * Tc + q) * Hc + col) = make_float2(o0 * inv, o1 * inv);
}

// ---------------------------------------------------------------------------
extern "C" void kernel_launch(void* const* d_in, const int* in_sizes, int n_in,
                              void* d_out, int out_size)
{
    (void)in_sizes; (void)n_in; (void)out_size;
    const float* x  = (const float*)d_in[0];
    const float* Wk = (const float*)d_in[1];
    const float* bk = (const float*)d_in[2];
    const float* Wq = (const float*)d_in[3];
    const float* bq = (const float*)d_in[4];
    const float* Wv = (const float*)d_in[5];
    const float* bv = (const float*)d_in[6];
    float* out = (float*)d_out;

    cudaFuncSetAttribute(proj_kernel, cudaFuncAttributeMaxDynamicSharedMemorySize, PSMEM);
    cudaFuncSetAttribute(attn_partial_kernel, cudaFuncAttributeMaxDynamicSharedMemorySize, ASMEM);

    prep_w_kernel<<<(3 * Dc * Hc / 4) / 256, 256>>>(Wq, Wk, Wv);

    proj_kernel<<<(Bc * Tc) / 128, 384, PSMEM>>>(x, bq, bk, bv);

    dim3 ag(SLOTS, Bc);
    attn_partial_kernel<<<ag, 128, ASMEM>>>();

    merge_kernel<<<(Bc * Tc) / 8, 256>>>(out);
}